// round 13
// baseline (speedup 1.0000x reference)
#include <cuda_runtime.h>
#include <math.h>
#include <float.h>
#include <stdint.h>
#include <stddef.h>

#define Bz 16
#define Tz 1024
#define Hz 1024
#define HHz 512
#define Sz 32
#define NHz 16
#define NLz 3
#define G4z 2048
#define LN_EPS 1e-7f

// ---------------- scratch ----------------
__device__ float g_xgf[(size_t)Bz * Tz * G4z];
__device__ float g_xgb[(size_t)Bz * Tz * G4z];
__device__ float g_enc[(size_t)Bz * Tz * Hz];
__device__ float g_hbuf[2 * 2 * Bz * HHz];
__device__ float g_feat[Bz * Sz * Hz];
__device__ float g_feat32[Bz * Sz * Hz];
__device__ float g_q[Bz * Sz * Hz];
__device__ float g_k[Bz * Sz * Hz];
__device__ float g_v[Bz * Sz * Hz];
__device__ float g_ctx[Bz * Sz * Hz];
__device__ float g_proj[Bz * Sz * Hz];
__device__ float g_att[Bz * Sz * Hz];
__device__ unsigned int g_bar[128];        // dir*64 -> 256B apart (distinct LTS slice)
__device__ unsigned int g_work[32];
__device__ unsigned int g_prog[16 * 64];   // grp*64 -> 256B apart
__device__ float g_hs32[(size_t)Bz * Tz * Hz];
__device__ float g_wihf32[(size_t)G4z * Hz];
__device__ float g_wihb32[(size_t)G4z * Hz];
__device__ float g_wq32[Hz * Hz];
__device__ float g_wk32[Hz * Hz];
__device__ float g_wv32[Hz * Hz];
__device__ float g_wo32[Hz * Hz];

// ---------------- helpers ----------------
__device__ __forceinline__ unsigned int f2tf32(float x) {
    unsigned int u;
    asm("cvt.rna.tf32.f32 %0, %1;" : "=r"(u) : "f"(x));
    return u;
}
__device__ __forceinline__ float tanh_fast(float x) {
    float y;
    asm("tanh.approx.f32 %0, %1;" : "=f"(y) : "f"(x));
    return y;
}
__device__ __forceinline__ float sigmoid_fast(float x) {
    return 0.5f * tanh_fast(0.5f * x) + 0.5f;
}
__device__ __forceinline__ void mma_tf32(float* d, const unsigned int* a,
                                         const unsigned int* b) {
    asm("mma.sync.aligned.m16n8k8.row.col.f32.tf32.tf32.f32 "
        "{%0,%1,%2,%3}, {%4,%5,%6,%7}, {%8,%9}, {%0,%1,%2,%3};"
        : "+f"(d[0]), "+f"(d[1]), "+f"(d[2]), "+f"(d[3])
        : "r"(a[0]), "r"(a[1]), "r"(a[2]), "r"(a[3]), "r"(b[0]), "r"(b[1]));
}
__device__ __forceinline__ void ldsm_x4(unsigned int* r, unsigned int addr) {
    asm volatile("ldmatrix.sync.aligned.m8n8.x4.shared.b16 {%0,%1,%2,%3}, [%4];"
                 : "=r"(r[0]), "=r"(r[1]), "=r"(r[2]), "=r"(r[3]) : "r"(addr));
}
__device__ __forceinline__ void cp_async16(void* dst, const void* src) {
    unsigned int d = (unsigned int)__cvta_generic_to_shared(dst);
    asm volatile("cp.async.cg.shared.global [%0], [%1], 16;" :: "r"(d), "l"(src));
}
__device__ __forceinline__ void cp_async4(void* dst, const void* src) {
    unsigned int d = (unsigned int)__cvta_generic_to_shared(dst);
    asm volatile("cp.async.ca.shared.global [%0], [%1], 4;" :: "r"(d), "l"(src));
}
#define CP_COMMIT() asm volatile("cp.async.commit_group;")
#define CP_WAIT2()  asm volatile("cp.async.wait_group 2;")
#define CP_WAIT1()  asm volatile("cp.async.wait_group 1;")

__device__ __forceinline__ void red_release(unsigned int* p, unsigned int v) {
    asm volatile("red.release.gpu.global.add.u32 [%0], %1;" :: "l"(p), "r"(v)
                 : "memory");
}
__device__ __forceinline__ unsigned int ld_acquire(const unsigned int* p) {
    unsigned int v;
    asm volatile("ld.acquire.gpu.global.u32 %0, [%1];" : "=r"(v) : "l"(p)
                 : "memory");
    return v;
}
// leader-poll barrier wait (cooperative-groups idiom): lane0 acquire-polls,
// bar.warp.sync provides memory ordering for the other lanes. NO trailing
// acquire (that dependent RT was R11's +478us regression).
__device__ __forceinline__ void bar_wait_warp(unsigned int* p,
                                              unsigned int target, int lane) {
    if (lane == 0) {
        while (ld_acquire(p) < target) { }
    }
    __syncwarp();
}

// ---------------- init ----------------
__global__ void init_kernel() {
    int tid = blockIdx.x * blockDim.x + threadIdx.x;
    if (tid < 128) g_bar[tid] = 0u;
    if (tid < 32) g_work[tid] = 0u;
    for (int i = tid; i < 16 * 64; i += gridDim.x * blockDim.x) g_prog[i] = 0u;
    for (int i = tid; i < 2 * 2 * Bz * HHz; i += gridDim.x * blockDim.x)
        g_hbuf[i] = 0.f;
}

// ---------------- tf32 pre-convert ----------------
__global__ void conv_pre3(const float* s0, float* d0, int n0,
                          const float* s1, float* d1, int n1,
                          const float* s2, float* d2, int n2) {
    int y = blockIdx.y;
    const float* s = (y == 0) ? s0 : (y == 1) ? s1 : s2;
    float* d = (y == 0) ? d0 : (y == 1) ? d1 : d2;
    int n4 = (y == 0) ? n0 : (y == 1) ? n1 : n2;
    int i = blockIdx.x * blockDim.x + threadIdx.x;
    int stride = gridDim.x * blockDim.x;
    for (; i < n4; i += stride) {
        float4 v = ((const float4*)s)[i];
        v.x = __uint_as_float(f2tf32(v.x));
        v.y = __uint_as_float(f2tf32(v.y));
        v.z = __uint_as_float(f2tf32(v.z));
        v.w = __uint_as_float(f2tf32(v.w));
        ((float4*)d)[i] = v;
    }
}
__global__ void conv_tf32_4(const float* s0, float* d0, const float* s1, float* d1,
                            const float* s2, float* d2, const float* s3, float* d3,
                            int n4) {
    const float* s = (blockIdx.y == 0) ? s0 : (blockIdx.y == 1) ? s1
                    : (blockIdx.y == 2) ? s2 : s3;
    float* d = (blockIdx.y == 0) ? d0 : (blockIdx.y == 1) ? d1
             : (blockIdx.y == 2) ? d2 : d3;
    int i = blockIdx.x * blockDim.x + threadIdx.x;
    int stride = gridDim.x * blockDim.x;
    for (; i < n4; i += stride) {
        float4 v = ((const float4*)s)[i];
        v.x = __uint_as_float(f2tf32(v.x));
        v.y = __uint_as_float(f2tf32(v.y));
        v.z = __uint_as_float(f2tf32(v.z));
        v.w = __uint_as_float(f2tf32(v.w));
        ((float4*)d)[i] = v;
    }
}

// inner compute step shared by both GEMM paths: one 32-wide k-chunk with LDSM
#define GEMM_CHUNK_LDSM(ab, bb2, aBaseOff, bBaseOff, ACC) do {               \
    unsigned int aB = (unsigned int)__cvta_generic_to_shared(ab) + aBaseOff; \
    unsigned int bB = (unsigned int)__cvta_generic_to_shared(bb2) + bBaseOff;\
    _Pragma("unroll")                                                        \
    for (int ks = 0; ks < 4; ++ks) {                                         \
        unsigned int koff = ks * 32;                                         \
        unsigned int afr[4][4];                                              \
        _Pragma("unroll")                                                    \
        for (int i = 0; i < 4; ++i) {                                        \
            unsigned int av[4];                                              \
            ldsm_x4(av, aB + (unsigned int)(i * 16 * LDP * 4) + koff);       \
            afr[i][0] = av[0]; afr[i][1] = av[2];                            \
            afr[i][2] = av[1]; afr[i][3] = av[3];                            \
        }                                                                    \
        unsigned int bv0[4], bv1[4];                                         \
        ldsm_x4(bv0, bB + koff);                                             \
        ldsm_x4(bv1, bB + (unsigned int)(16 * LDP * 4) + koff);              \
        _Pragma("unroll")                                                    \
        for (int i = 0; i < 4; ++i) {                                        \
            mma_tf32(ACC[i][0], afr[i], &bv0[0]);                            \
            mma_tf32(ACC[i][1], afr[i], &bv0[2]);                            \
            mma_tf32(ACC[i][2], afr[i], &bv1[0]);                            \
            mma_tf32(ACC[i][3], afr[i], &bv1[2]);                            \
        }                                                                    \
    }                                                                        \
} while (0)

// ---------------- FUSED gate-GEMM + bi-LSTM ---------------------------------
#define LDP 36
#define NLSTM 128
#define FSM_BYTES (3 * 2 * 128 * LDP * 4)   // 110592
__global__ void __launch_bounds__(256, 2) fused_kernel(
    const float* __restrict__ A,
    const float* __restrict__ Wf, const float* __restrict__ Wb,
    const float* __restrict__ bf, const float* __restrict__ bb,
    float* __restrict__ xgf, float* __restrict__ xgb,
    const float* __restrict__ whh_f, const float* __restrict__ whh_b,
    float* __restrict__ enc, float* __restrict__ hbuf)
{
    extern __shared__ float smem[];
    int tid = threadIdx.x, lane = tid & 31, warp = tid >> 5;

    if (blockIdx.x >= NLSTM) {
        // ================= GEMM worker role =================
        float* a_s = smem;
        float* b_s = smem + 3 * 128 * LDP;
        __shared__ unsigned int s_w;
        const int K = Hz, N = G4z;

        int warp_m = warp & 1, warp_n = warp >> 1;
        int tile = lane >> 3, tr = lane & 7;
        int rowsel = (tile & 2) ? 8 : 0;
        int colsel = (tile & 1) ? 4 : 0;
        unsigned int aOff = (unsigned int)(((warp_m * 64 + rowsel + tr) * LDP
                                            + colsel) * 4);
        unsigned int bOff = (unsigned int)(((warp_n * 32 + rowsel + tr) * LDP
                                            + colsel) * 4);
        int qr = lane >> 2, qc = lane & 3;

        for (;;) {
            if (tid == 0) s_w = atomicAdd(&g_work[0], 1u);
            __syncthreads();
            unsigned int w = s_w;
            if (w >= 4096u) break;

            int grp = w >> 8;
            int within = w & 255;
            int dir = grp & 1;
            int c = grp >> 1;
            int chunk = dir ? (7 - c) : c;
            int b = within >> 4;
            int nt = within & 15;
            int m0 = b * 1024 + chunk * 128;
            int n0 = nt * 128;
            const float* W = dir ? Wb : Wf;
            const float* bias = dir ? bb : bf;
            float* C = dir ? xgb : xgf;

            float acc[4][4][4];
#pragma unroll
            for (int i = 0; i < 4; ++i)
#pragma unroll
                for (int j = 0; j < 4; ++j)
#pragma unroll
                    for (int r = 0; r < 4; ++r) acc[i][j][r] = 0.f;

#define ISSUE(chunk_, stage_) do {                                         \
        int kofs = (chunk_) * 32;                                          \
        float* as = a_s + (stage_) * 128 * LDP;                            \
        float* bs = b_s + (stage_) * 128 * LDP;                            \
        _Pragma("unroll")                                                  \
        for (int i_ = 0; i_ < 4; ++i_) {                                   \
            int f_ = tid + 256 * i_;                                       \
            int row_ = f_ >> 3, q_ = f_ & 7;                               \
            cp_async16(&as[row_ * LDP + q_ * 4],                           \
                       &A[(size_t)(m0 + row_) * K + kofs + q_ * 4]);       \
            cp_async16(&bs[row_ * LDP + q_ * 4],                           \
                       &W[(size_t)(n0 + row_) * K + kofs + q_ * 4]);       \
        }                                                                  \
        CP_COMMIT();                                                       \
    } while (0)

            ISSUE(0, 0);
            ISSUE(1, 1);
            for (int kt = 0; kt < 32; ++kt) {
                if (kt + 2 < 32) {
                    ISSUE(kt + 2, (kt + 2) % 3);
                } else {
                    CP_COMMIT();
                }
                CP_WAIT2();
                __syncthreads();
                float* ab = a_s + (kt % 3) * 128 * LDP;
                float* bb2 = b_s + (kt % 3) * 128 * LDP;
                GEMM_CHUNK_LDSM(ab, bb2, aOff, bOff, acc);
                __syncthreads();
            }

#pragma unroll
            for (int i = 0; i < 4; ++i) {
                int r0 = m0 + warp_m * 64 + i * 16 + qr;
#pragma unroll
                for (int j = 0; j < 4; ++j) {
                    int c0 = n0 + warp_n * 32 + j * 8 + qc * 2;
                    float v0 = bias[c0], v1 = bias[c0 + 1];
                    C[(size_t)r0 * N + c0]           = acc[i][j][0] + v0;
                    C[(size_t)r0 * N + c0 + 1]       = acc[i][j][1] + v1;
                    C[(size_t)(r0 + 8) * N + c0]     = acc[i][j][2] + v0;
                    C[(size_t)(r0 + 8) * N + c0 + 1] = acc[i][j][3] + v1;
                }
            }
            __syncthreads();
            if (tid == 0) red_release(&g_prog[grp * 64], 1u);
        }
        return;
    }

    // ================= LSTM role =================
    float* h_sm  = smem;                 // 16 x 516
    float* red   = h_sm + 16 * 516;      // [8][32][17]
    float* c_sm  = red + 8 * 32 * 17;    // 128
    float* xg_sm = c_sm + 128;           // [2][4*128] prefetched gates

    int dir = blockIdx.x >> 6;
    int slice = blockIdx.x & 63;
    int j0 = slice << 3;
    const float* whh = dir ? whh_b : whh_f;
    const float* xg  = dir ? xgb : xgf;

    int qr = lane >> 2, qc = lane & 3;
    int kbase = warp << 6;
    int b = tid >> 3, jj = tid & 7;

    unsigned int wreg[8][4][2];
#pragma unroll
    for (int s = 0; s < 8; ++s)
#pragma unroll
        for (int j = 0; j < 4; ++j) {
            const float* wr = whh + (size_t)(j * HHz + j0 + qr) * HHz
                              + kbase + s * 8;
            wreg[s][j][0] = f2tf32(wr[qc]);
            wreg[s][j][1] = f2tf32(wr[qc + 4]);
        }

    if (tid < 128) c_sm[tid] = 0.f;
    __syncthreads();

    unsigned int* barp = &g_bar[dir * 64];

    // prologue: load step-0 h slab (zeros), gate chunk 0, prefetch xg step 0
    {
        const float* hgr = hbuf + (size_t)(dir * 2 + 0) * Bz * HHz;
        int q = lane & 15, bh = lane >> 4;
#pragma unroll
        for (int i = 0; i < 8; ++i) {
            int bb2 = i * 2 + bh;
            *(float4*)&h_sm[bb2 * 516 + kbase + q * 4] =
                *(const float4*)&hgr[bb2 * HHz + kbase + q * 4];
        }
        __syncwarp();

        bar_wait_warp(&g_prog[(0 * 2 + dir) * 64], 256u, lane);
        if (tid < 128) {
            int t0 = dir ? (Tz - 1) : 0;
            const float* xr = xg + ((size_t)b * Tz + t0) * G4z + j0 + jj;
            cp_async4(&xg_sm[tid],       xr);
            cp_async4(&xg_sm[128 + tid], xr + HHz);
            cp_async4(&xg_sm[256 + tid], xr + 2 * HHz);
            cp_async4(&xg_sm[384 + tid], xr + 3 * HHz);
        }
        CP_COMMIT();
    }

    for (int step = 0; step < Tz; ++step) {
        int par = step & 1;
        int t = dir ? (Tz - 1 - step) : step;

        // gate + prefetch xg for step+1 (consumed next iteration)
        if (step + 1 < Tz) {
            if (((step + 1) & 127) == 0) {
                bar_wait_warp(&g_prog[(((step + 1) >> 7) * 2 + dir) * 64],
                              256u, lane);
            }
            if (tid < 128) {
                int t1 = dir ? (Tz - 1 - (step + 1)) : (step + 1);
                const float* xr = xg + ((size_t)b * Tz + t1) * G4z + j0 + jj;
                float* xb = xg_sm + ((step + 1) & 1) * 512;
                cp_async4(&xb[tid],       xr);
                cp_async4(&xb[128 + tid], xr + HHz);
                cp_async4(&xb[256 + tid], xr + 2 * HHz);
                cp_async4(&xb[384 + tid], xr + 3 * HHz);
            }
        }
        CP_COMMIT();
        CP_WAIT1();   // current step's xg (committed last iteration) is ready

        float acc[4][4];
#pragma unroll
        for (int j = 0; j < 4; ++j)
#pragma unroll
            for (int r = 0; r < 4; ++r) acc[j][r] = 0.f;

#pragma unroll
        for (int s = 0; s < 8; ++s) {
            const float* hb = h_sm + kbase + s * 8;
            unsigned int a[4];
            a[0] = __float_as_uint(hb[qr * 516 + qc]);
            a[1] = __float_as_uint(hb[(qr + 8) * 516 + qc]);
            a[2] = __float_as_uint(hb[qr * 516 + qc + 4]);
            a[3] = __float_as_uint(hb[(qr + 8) * 516 + qc + 4]);
#pragma unroll
            for (int j = 0; j < 4; ++j)
                mma_tf32(acc[j], a, wreg[s][j]);
        }

        float* rw = red + warp * 32 * 17;
#pragma unroll
        for (int j = 0; j < 4; ++j) {
            int n0i = j * 8 + qc * 2;
            rw[n0i * 17 + qr]           = acc[j][0];
            rw[(n0i + 1) * 17 + qr]     = acc[j][1];
            rw[n0i * 17 + qr + 8]       = acc[j][2];
            rw[(n0i + 1) * 17 + qr + 8] = acc[j][3];
        }
        __syncthreads();

        float h = 0.f;
        if (tid < 128) {
            const float* xb = xg_sm + (step & 1) * 512;
            float gi = xb[tid], gf = xb[128 + tid];
            float gg = xb[256 + tid], go = xb[384 + tid];
#pragma unroll
            for (int w = 0; w < 8; ++w) {
                const float* rp = red + w * 32 * 17;
                gi += rp[jj * 17 + b];
                gf += rp[(8 + jj) * 17 + b];
                gg += rp[(16 + jj) * 17 + b];
                go += rp[(24 + jj) * 17 + b];
            }
            float i_ = sigmoid_fast(gi);
            float f_ = sigmoid_fast(gf);
            float g_ = tanh_fast(gg);
            float o_ = sigmoid_fast(go);
            float c = f_ * c_sm[tid] + i_ * g_;
            c_sm[tid] = c;
            h = o_ * tanh_fast(c);
            float* hw = hbuf + (size_t)(dir * 2 + (par ^ 1)) * Bz * HHz;
            hw[b * HHz + j0 + jj] = __uint_as_float(f2tf32(h));
        }

        if (step + 1 < Tz) {
            __syncthreads();
            if (tid == 0) red_release(barp, 1u);
            if (tid < 128)
                enc[((size_t)b * Tz + t) * Hz + dir * HHz + j0 + jj] = h;
            unsigned int target = (unsigned int)(step + 1) * 64u;
            bar_wait_warp(barp, target, lane);
            const float* hgr = hbuf + (size_t)(dir * 2 + (par ^ 1)) * Bz * HHz;
            int q = lane & 15, bh = lane >> 4;
#pragma unroll
            for (int i = 0; i < 8; ++i) {
                int bb2 = i * 2 + bh;
                *(float4*)&h_sm[bb2 * 516 + kbase + q * 4] =
                    *(const float4*)&hgr[bb2 * HHz + kbase + q * 4];
            }
            __syncwarp();
        } else {
            if (tid < 128)
                enc[((size_t)b * Tz + t) * Hz + dir * HHz + j0 + jj] = h;
        }
    }
}

// ---------------- pipelined tf32 GEMM 128x128, z-fused up to 3 -------------
#define STG 3
__global__ void __launch_bounds__(256) gemm_pipe(
    const float* __restrict__ A,
    const float* __restrict__ W0, const float* __restrict__ W1,
    const float* __restrict__ W2,
    const float* __restrict__ b0, const float* __restrict__ b1,
    const float* __restrict__ b2,
    float* __restrict__ C0, float* __restrict__ C1, float* __restrict__ C2,
    int M, int N, int K)
{
    extern __shared__ float sm[];
    float* a_s = sm;
    float* b_s = sm + STG * 128 * LDP;

    int z = blockIdx.z;
    const float* W   = (z == 0) ? W0 : (z == 1) ? W1 : W2;
    const float* bias= (z == 0) ? b0 : (z == 1) ? b1 : b2;
    float* C         = (z == 0) ? C0 : (z == 1) ? C1 : C2;

    int tid = threadIdx.x;
    int lane = tid & 31, warp = tid >> 5;
    int warp_m = warp & 1, warp_n = warp >> 1;
    int m0 = blockIdx.y * 128, n0 = blockIdx.x * 128;
    int qr = lane >> 2, qc = lane & 3;
    int nk = K >> 5;

    int tile = lane >> 3, tr = lane & 7;
    int rowsel = (tile & 2) ? 8 : 0;
    int colsel = (tile & 1) ? 4 : 0;
    unsigned int aOff = (unsigned int)(((warp_m * 64 + rowsel + tr) * LDP
                                        + colsel) * 4);
    unsigned int bOff = (unsigned int)(((warp_n * 32 + rowsel + tr) * LDP
                                        + colsel) * 4);

    float acc[4][4][4];
#pragma unroll
    for (int i = 0; i < 4; ++i)
#pragma unroll
        for (int j = 0; j < 4; ++j)
#pragma unroll
            for (int r = 0; r < 4; ++r) acc[i][j][r] = 0.f;

#define ISSUE_P(chunk, stage) do {                                         \
        int kofs = (chunk) * 32;                                           \
        float* as = a_s + (stage) * 128 * LDP;                             \
        float* bs = b_s + (stage) * 128 * LDP;                             \
        _Pragma("unroll")                                                  \
        for (int i_ = 0; i_ < 4; ++i_) {                                   \
            int f_ = tid + 256 * i_;                                       \
            int row_ = f_ >> 3, q_ = f_ & 7;                               \
            cp_async16(&as[row_ * LDP + q_ * 4],                           \
                       &A[(size_t)(m0 + row_) * K + kofs + q_ * 4]);       \
            cp_async16(&bs[row_ * LDP + q_ * 4],                           \
                       &W[(size_t)(n0 + row_) * K + kofs + q_ * 4]);       \
        }                                                                  \
        CP_COMMIT();                                                       \
    } while (0)

    ISSUE_P(0, 0);
    ISSUE_P(1, 1);

    for (int kt = 0; kt < nk; ++kt) {
        if (kt + 2 < nk) {
            ISSUE_P(kt + 2, (kt + 2) % STG);
        } else {
            CP_COMMIT();
        }
        CP_WAIT2();
        __syncthreads();

        float* ab = a_s + (kt % STG) * 128 * LDP;
        float* bb = b_s + (kt % STG) * 128 * LDP;
        GEMM_CHUNK_LDSM(ab, bb, aOff, bOff, acc);
        __syncthreads();
    }

#pragma unroll
    for (int i = 0; i < 4; ++i) {
        int r0 = m0 + warp_m * 64 + i * 16 + qr;
#pragma unroll
        for (int j = 0; j < 4; ++j) {
            int c0 = n0 + warp_n * 32 + j * 8 + qc * 2;
            float bb0 = bias[c0], bb1 = bias[c0 + 1];
            C[(size_t)r0 * N + c0]           = acc[i][j][0] + bb0;
            C[(size_t)r0 * N + c0 + 1]       = acc[i][j][1] + bb1;
            C[(size_t)(r0 + 8) * N + c0]     = acc[i][j][2] + bb0;
            C[(size_t)(r0 + 8) * N + c0 + 1] = acc[i][j][3] + bb1;
        }
    }
}

// ---------------- span mean pool + layer norm ------------------------------
__global__ void __launch_bounds__(256) pool_ln_kernel(
    const float* __restrict__ enc, const int* __restrict__ heads,
    const int* __restrict__ tails, const float* __restrict__ g,
    const float* __restrict__ b, float* __restrict__ feat,
    float* __restrict__ feat32)
{
    __shared__ float rs[256], rq[256];
    int bs = blockIdx.x;
    int bb = bs >> 5;
    int tid = threadIdx.x;

    int head = heads[bs], tail = tails[bs];
    int s0 = head + 1; if (s0 < 0) s0 = 0;
    int s1 = tail; if (s1 > Tz) s1 = Tz;
    int n = s1 - s0; if (n < 0) n = 0;
    float inv = 1.f / (float)(n > 0 ? n : 1);

    float v[4];
#pragma unroll
    for (int i = 0; i < 4; ++i) v[i] = 0.f;
    for (int t = s0; t < s1; ++t) {
        const float* row = enc + ((size_t)bb * Tz + t) * Hz;
#pragma unroll
        for (int i = 0; i < 4; ++i) v[i] += row[tid + 256 * i];
    }
#pragma unroll
    for (int i = 0; i < 4; ++i) v[i] *= inv;

    float s = v[0] + v[1] + v[2] + v[3];
    float q = v[0]*v[0] + v[1]*v[1] + v[2]*v[2] + v[3]*v[3];
    rs[tid] = s; rq[tid] = q;
    __syncthreads();
    for (int off = 128; off > 0; off >>= 1) {
        if (tid < off) { rs[tid] += rs[tid + off]; rq[tid] += rq[tid + off]; }
        __syncthreads();
    }
    float mu = rs[0] * (1.f / Hz);
    float var = rq[0] * (1.f / Hz) - mu * mu;
    float rstd = rsqrtf(var + LN_EPS);

    float* out = feat + (size_t)bs * Hz;
    float* out32 = feat32 + (size_t)bs * Hz;
#pragma unroll
    for (int i = 0; i < 4; ++i) {
        int c = tid + 256 * i;
        float y = (v[i] - mu) * rstd * g[c] + b[c];
        out[c] = y;
        out32[c] = __uint_as_float(f2tf32(y));
    }
}

// ---------------- span self-attention --------------------------------------
__global__ void __launch_bounds__(256) attn_kernel(
    const float* __restrict__ Q, const float* __restrict__ K,
    const float* __restrict__ V, const int* __restrict__ amask,
    float* __restrict__ ctx)
{
    __shared__ float q_sm[Sz * 64], k_sm[Sz * 64], v_sm[Sz * 64];
    __shared__ int m_sm[Sz];
    int bh = blockIdx.x;
    int bb = bh >> 4, h = bh & 15;
    int tid = threadIdx.x, lane = tid & 31, warp = tid >> 5;

    for (int idx = tid; idx < Sz * 64; idx += 256) {
        int s = idx >> 6, d = idx & 63;
        size_t src = ((size_t)bb * Sz + s) * Hz + h * 64 + d;
        q_sm[idx] = Q[src];
        k_sm[idx] = K[src];
        v_sm[idx] = V[src];
    }
    if (tid < Sz) m_sm[tid] = amask[bb * Sz + tid];
    __syncthreads();

#pragma unroll
    for (int r = 0; r < 4; ++r) {
        int qi = warp + r * 8;
        int qm = m_sm[qi];
        float sc = 0.f;
#pragma unroll
        for (int d = 0; d < 64; ++d)
            sc += q_sm[qi * 64 + d] * k_sm[lane * 64 + d];
        sc *= 0.125f;
        int km = m_sm[lane];
        int valid = qm & km;
        if (!valid) sc = -FLT_MAX;
        float mx = sc;
#pragma unroll
        for (int o = 16; o > 0; o >>= 1)
            mx = fmaxf(mx, __shfl_xor_sync(0xffffffffu, mx, o));
        float e = __expf(sc - mx);
        float sum = e;
#pragma unroll
        for (int o = 16; o > 0; o >>= 1)
            sum += __shfl_xor_sync(0xffffffffu, sum, o);
        float p = e / sum;
        if (!valid) p = 0.f;
        float a0 = 0.f, a1 = 0.f;
#pragma unroll
        for (int kk = 0; kk < 32; ++kk) {
            float pk = __shfl_sync(0xffffffffu, p, kk);
            a0 += pk * v_sm[kk * 64 + lane];
            a1 += pk * v_sm[kk * 64 + lane + 32];
        }
        size_t dst = ((size_t)bb * Sz + qi) * Hz + h * 64;
        ctx[dst + lane] = __uint_as_float(f2tf32(a0));
        ctx[dst + lane + 32] = __uint_as_float(f2tf32(a1));
    }
}

// ---------------- residual add + layer norm --------------------------------
__global__ void __launch_bounds__(256) addln_kernel(
    const float* __restrict__ proj, const float* __restrict__ feat,
    const float* __restrict__ g, const float* __restrict__ b,
    float* __restrict__ out)
{
    __shared__ float rs[256], rq[256];
    int row = blockIdx.x, tid = threadIdx.x;
    const float* p = proj + (size_t)row * Hz;
    const float* f = feat + (size_t)row * Hz;
    float v[4];
#pragma unroll
    for (int i = 0; i < 4; ++i) {
        int c = tid + 256 * i;
        v[i] = p[c] + f[c];
    }
    float s = v[0] + v[1] + v[2] + v[3];
    float q = v[0]*v[0] + v[1]*v[1] + v[2]*v[2] + v[3]*v[3];
    rs[tid] = s; rq[tid] = q;
    __syncthreads();
    for (int off = 128; off > 0; off >>= 1) {
        if (tid < off) { rs[tid] += rs[tid + off]; rq[tid] += rq[tid + off]; }
        __syncthreads();
    }
    float mu = rs[0] * (1.f / Hz);
    float var = rq[0] * (1.f / Hz) - mu * mu;
    float rstd = rsqrtf(var + LN_EPS);
    float* o = out + (size_t)row * Hz;
#pragma unroll
    for (int i = 0; i < 4; ++i) {
        int c = tid + 256 * i;
        o[c] = (v[i] - mu) * rstd * g[c] + b[c];
    }
}

// ---------------- classifier ------------------------------------------------
__global__ void __launch_bounds__(128) cls_kernel(
    const float* __restrict__ att, const float* __restrict__ wc,
    const float* __restrict__ bc, float* __restrict__ out)
{
    __shared__ float red[128];
    int row = blockIdx.x, tid = threadIdx.x;
    const float* a = att + (size_t)row * Hz;
    for (int l = 0; l < NLz; ++l) {
        const float* w = wc + (size_t)l * Hz;
        float s = 0.f;
#pragma unroll
        for (int i = 0; i < 8; ++i)
            s += a[tid + 128 * i] * w[tid + 128 * i];
        red[tid] = s;
        __syncthreads();
        for (int off = 64; off > 0; off >>= 1) {
            if (tid < off) red[tid] += red[tid + off];
            __syncthreads();
        }
        if (tid == 0) out[row * NLz + l] = red[0] + bc[l];
        __syncthreads();
    }
}

// ---------------- launch -----------------------------------------------------
extern "C" void kernel_launch(void* const* d_in, const int* in_sizes, int n_in,
                              void* d_out, int out_size) {
    const float* hs     = (const float*)d_in[0];
    const float* w_ih_f = (const float*)d_in[1];
    const float* w_hh_f = (const float*)d_in[2];
    const float* b_f    = (const float*)d_in[3];
    const float* w_ih_b = (const float*)d_in[4];
    const float* w_hh_b = (const float*)d_in[5];
    const float* b_b    = (const float*)d_in[6];
    const float* ln_g   = (const float*)d_in[7];
    const float* ln_b   = (const float*)d_in[8];
    const float* wq     = (const float*)d_in[9];
    const float* bq     = (const float*)d_in[10];
    const float* wk     = (const float*)d_in[11];
    const float* bk     = (const float*)d_in[12];
    const float* wv     = (const float*)d_in[13];
    const float* bv     = (const float*)d_in[14];
    const float* wo     = (const float*)d_in[15];
    const float* bo     = (const float*)d_in[16];
    const float* aln_g  = (const float*)d_in[17];
    const float* aln_b  = (const float*)d_in[18];
    const float* wc     = (const float*)d_in[19];
    const float* bc     = (const float*)d_in[20];
    const int* heads    = (const int*)d_in[21];
    const int* tails    = (const int*)d_in[22];
    const int* amask    = (const int*)d_in[23];
    float* out = (float*)d_out;

    float *xgf, *xgb, *enc, *hbuf, *feat, *feat32, *q, *k, *v, *ctx, *proj, *att;
    float *hs32, *wihf32, *wihb32, *wq32, *wk32, *wv32, *wo32;
    cudaGetSymbolAddress((void**)&xgf,  g_xgf);
    cudaGetSymbolAddress((void**)&xgb,  g_xgb);
    cudaGetSymbolAddress((void**)&enc,  g_enc);
    cudaGetSymbolAddress((void**)&hbuf, g_hbuf);
    cudaGetSymbolAddress((void**)&feat, g_feat);
    cudaGetSymbolAddress((void**)&feat32, g_feat32);
    cudaGetSymbolAddress((void**)&q,    g_q);
    cudaGetSymbolAddress((void**)&k,    g_k);
    cudaGetSymbolAddress((void**)&v,    g_v);
    cudaGetSymbolAddress((void**)&ctx,  g_ctx);
    cudaGetSymbolAddress((void**)&proj, g_proj);
    cudaGetSymbolAddress((void**)&att,  g_att);
    cudaGetSymbolAddress((void**)&hs32,   g_hs32);
    cudaGetSymbolAddress((void**)&wihf32, g_wihf32);
    cudaGetSymbolAddress((void**)&wihb32, g_wihb32);
    cudaGetSymbolAddress((void**)&wq32,   g_wq32);
    cudaGetSymbolAddress((void**)&wk32,   g_wk32);
    cudaGetSymbolAddress((void**)&wv32,   g_wv32);
    cudaGetSymbolAddress((void**)&wo32,   g_wo32);

    cudaFuncSetAttribute(fused_kernel,
                         cudaFuncAttributeMaxDynamicSharedMemorySize, FSM_BYTES);
    const int gemm_smem = STG * 128 * LDP * 2 * 4;
    cudaFuncSetAttribute(gemm_pipe,
                         cudaFuncAttributeMaxDynamicSharedMemorySize, gemm_smem);

    init_kernel<<<32, 256>>>();                                           // 1
    conv_pre3<<<dim3(512, 3), 256>>>(hs, hs32, (Bz * Tz * Hz) / 4,
                                     w_ih_f, wihf32, (G4z * Hz) / 4,
                                     w_ih_b, wihb32, (G4z * Hz) / 4);     // 2
    conv_tf32_4<<<dim3(128, 4), 256>>>(wq, wq32, wk, wk32, wv, wv32,
                                       wo, wo32, (Hz * Hz) / 4);          // 3
    fused_kernel<<<296, 256, FSM_BYTES>>>(
        hs32, wihf32, wihb32, b_f, b_b, xgf, xgb,
        w_hh_f, w_hh_b, enc, hbuf);                                       // 4
    pool_ln_kernel<<<Bz * Sz, 256>>>(enc, heads, tails, ln_g, ln_b,
                                     feat, feat32);                       // 5
    gemm_pipe<<<dim3(Hz / 128, (Bz * Sz) / 128, 3), 256, gemm_smem>>>(
        feat32, wq32, wk32, wv32, bq, bk, bv,
        q, k, v, Bz * Sz, Hz, Hz);                                        // 6
    attn_kernel<<<Bz * NHz, 256>>>(q, k, v, amask, ctx);                  // 7
    gemm_pipe<<<dim3(Hz / 128, (Bz * Sz) / 128, 1), 256, gemm_smem>>>(
        ctx, wo32, nullptr, nullptr, bo, nullptr, nullptr,
        proj, nullptr, nullptr, Bz * Sz, Hz, Hz);                         // 8
    addln_kernel<<<Bz * Sz, 256>>>(proj, feat, aln_g, aln_b, att);        // 9
    cls_kernel<<<Bz * Sz, 128>>>(att, wc, bc, out);                       // 10
}

// round 14
// speedup vs baseline: 1.0907x; 1.0907x over previous
#include <cuda_runtime.h>
#include <math.h>
#include <float.h>
#include <stdint.h>
#include <stddef.h>

#define Bz 16
#define Tz 1024
#define Hz 1024
#define HHz 512
#define Sz 32
#define NHz 16
#define NLz 3
#define G4z 2048
#define LN_EPS 1e-7f

// ---------------- scratch ----------------
__device__ float g_xgf[(size_t)Bz * Tz * G4z];
__device__ float g_xgb[(size_t)Bz * Tz * G4z];
__device__ float g_enc[(size_t)Bz * Tz * Hz];
__device__ float g_hbuf[2 * 2 * Bz * HHz];
__device__ float g_feat[Bz * Sz * Hz];
__device__ float g_feat32[Bz * Sz * Hz];
__device__ float g_q[Bz * Sz * Hz];
__device__ float g_k[Bz * Sz * Hz];
__device__ float g_v[Bz * Sz * Hz];
__device__ float g_ctx[Bz * Sz * Hz];
__device__ float g_proj[Bz * Sz * Hz];
__device__ float g_att[Bz * Sz * Hz];
__device__ unsigned int g_bar[128];        // dir*64 -> 256B apart
__device__ unsigned int g_work[32];
__device__ unsigned int g_prog[16 * 64];   // grp*64 -> 256B apart
__device__ float g_hs32[(size_t)Bz * Tz * Hz];
__device__ float g_wihf32[(size_t)G4z * Hz];
__device__ float g_wihb32[(size_t)G4z * Hz];
__device__ float g_wq32[Hz * Hz];
__device__ float g_wk32[Hz * Hz];
__device__ float g_wv32[Hz * Hz];
__device__ float g_wo32[Hz * Hz];

// ---------------- helpers ----------------
__device__ __forceinline__ unsigned int f2tf32(float x) {
    unsigned int u;
    asm("cvt.rna.tf32.f32 %0, %1;" : "=r"(u) : "f"(x));
    return u;
}
__device__ __forceinline__ float tanh_fast(float x) {
    float y;
    asm("tanh.approx.f32 %0, %1;" : "=f"(y) : "f"(x));
    return y;
}
__device__ __forceinline__ float sigmoid_fast(float x) {
    return 0.5f * tanh_fast(0.5f * x) + 0.5f;
}
__device__ __forceinline__ void mma_tf32(float* d, const unsigned int* a,
                                         const unsigned int* b) {
    asm("mma.sync.aligned.m16n8k8.row.col.f32.tf32.tf32.f32 "
        "{%0,%1,%2,%3}, {%4,%5,%6,%7}, {%8,%9}, {%0,%1,%2,%3};"
        : "+f"(d[0]), "+f"(d[1]), "+f"(d[2]), "+f"(d[3])
        : "r"(a[0]), "r"(a[1]), "r"(a[2]), "r"(a[3]), "r"(b[0]), "r"(b[1]));
}
__device__ __forceinline__ void ldsm_x4(unsigned int* r, unsigned int addr) {
    asm volatile("ldmatrix.sync.aligned.m8n8.x4.shared.b16 {%0,%1,%2,%3}, [%4];"
                 : "=r"(r[0]), "=r"(r[1]), "=r"(r[2]), "=r"(r[3]) : "r"(addr));
}
__device__ __forceinline__ void cp_async16(void* dst, const void* src) {
    unsigned int d = (unsigned int)__cvta_generic_to_shared(dst);
    asm volatile("cp.async.cg.shared.global [%0], [%1], 16;" :: "r"(d), "l"(src));
}
__device__ __forceinline__ void cp_async4(void* dst, const void* src) {
    unsigned int d = (unsigned int)__cvta_generic_to_shared(dst);
    asm volatile("cp.async.ca.shared.global [%0], [%1], 4;" :: "r"(d), "l"(src));
}
#define CP_COMMIT() asm volatile("cp.async.commit_group;")
#define CP_WAIT1()  asm volatile("cp.async.wait_group 1;")

__device__ __forceinline__ void red_release(unsigned int* p, unsigned int v) {
    asm volatile("red.release.gpu.global.add.u32 [%0], %1;" :: "l"(p), "r"(v)
                 : "memory");
}
__device__ __forceinline__ unsigned int ld_acquire(const unsigned int* p) {
    unsigned int v;
    asm volatile("ld.acquire.gpu.global.u32 %0, [%1];" : "=r"(v) : "l"(p)
                 : "memory");
    return v;
}

// ---------------- init ----------------
__global__ void init_kernel() {
    int tid = blockIdx.x * blockDim.x + threadIdx.x;
    if (tid < 128) g_bar[tid] = 0u;
    if (tid < 32) g_work[tid] = 0u;
    for (int i = tid; i < 16 * 64; i += gridDim.x * blockDim.x) g_prog[i] = 0u;
    for (int i = tid; i < 2 * 2 * Bz * HHz; i += gridDim.x * blockDim.x)
        g_hbuf[i] = 0.f;
}

// ---------------- tf32 pre-convert ----------------
__global__ void conv_pre3(const float* s0, float* d0, int n0,
                          const float* s1, float* d1, int n1,
                          const float* s2, float* d2, int n2) {
    int y = blockIdx.y;
    const float* s = (y == 0) ? s0 : (y == 1) ? s1 : s2;
    float* d = (y == 0) ? d0 : (y == 1) ? d1 : d2;
    int n4 = (y == 0) ? n0 : (y == 1) ? n1 : n2;
    int i = blockIdx.x * blockDim.x + threadIdx.x;
    int stride = gridDim.x * blockDim.x;
    for (; i < n4; i += stride) {
        float4 v = ((const float4*)s)[i];
        v.x = __uint_as_float(f2tf32(v.x));
        v.y = __uint_as_float(f2tf32(v.y));
        v.z = __uint_as_float(f2tf32(v.z));
        v.w = __uint_as_float(f2tf32(v.w));
        ((float4*)d)[i] = v;
    }
}
__global__ void conv_tf32_4(const float* s0, float* d0, const float* s1, float* d1,
                            const float* s2, float* d2, const float* s3, float* d3,
                            int n4) {
    const float* s = (blockIdx.y == 0) ? s0 : (blockIdx.y == 1) ? s1
                    : (blockIdx.y == 2) ? s2 : s3;
    float* d = (blockIdx.y == 0) ? d0 : (blockIdx.y == 1) ? d1
             : (blockIdx.y == 2) ? d2 : d3;
    int i = blockIdx.x * blockDim.x + threadIdx.x;
    int stride = gridDim.x * blockDim.x;
    for (; i < n4; i += stride) {
        float4 v = ((const float4*)s)[i];
        v.x = __uint_as_float(f2tf32(v.x));
        v.y = __uint_as_float(f2tf32(v.y));
        v.z = __uint_as_float(f2tf32(v.z));
        v.w = __uint_as_float(f2tf32(v.w));
        ((float4*)d)[i] = v;
    }
}

// inner compute step shared by both GEMM paths: one 32-wide k-chunk with LDSM
#define GEMM_CHUNK_LDSM(ab, bb2, aBaseOff, bBaseOff, ACC) do {               \
    unsigned int aB = (unsigned int)__cvta_generic_to_shared(ab) + aBaseOff; \
    unsigned int bB = (unsigned int)__cvta_generic_to_shared(bb2) + bBaseOff;\
    _Pragma("unroll")                                                        \
    for (int ks = 0; ks < 4; ++ks) {                                         \
        unsigned int koff = ks * 32;                                         \
        unsigned int afr[4][4];                                              \
        _Pragma("unroll")                                                    \
        for (int i = 0; i < 4; ++i) {                                        \
            unsigned int av[4];                                              \
            ldsm_x4(av, aB + (unsigned int)(i * 16 * LDP * 4) + koff);       \
            afr[i][0] = av[0]; afr[i][1] = av[2];                            \
            afr[i][2] = av[1]; afr[i][3] = av[3];                            \
        }                                                                    \
        unsigned int bv0[4], bv1[4];                                         \
        ldsm_x4(bv0, bB + koff);                                             \
        ldsm_x4(bv1, bB + (unsigned int)(16 * LDP * 4) + koff);              \
        _Pragma("unroll")                                                    \
        for (int i = 0; i < 4; ++i) {                                        \
            mma_tf32(ACC[i][0], afr[i], &bv0[0]);                            \
            mma_tf32(ACC[i][1], afr[i], &bv0[2]);                            \
            mma_tf32(ACC[i][2], afr[i], &bv1[0]);                            \
            mma_tf32(ACC[i][3], afr[i], &bv1[2]);                            \
        }                                                                    \
    }                                                                        \
} while (0)

// ---------------- FUSED gate-GEMM + bi-LSTM ---------------------------------
#define LDP 36
#define NLSTM 128
#define FSM_BYTES (3 * 2 * 128 * LDP * 4)   // 110592
__global__ void __launch_bounds__(256, 2) fused_kernel(
    const float* __restrict__ A,
    const float* __restrict__ Wf, const float* __restrict__ Wb,
    const float* __restrict__ bf, const float* __restrict__ bb,
    float* __restrict__ xgf, float* __restrict__ xgb,
    const float* __restrict__ whh_f, const float* __restrict__ whh_b,
    float* __restrict__ enc, float* __restrict__ hbuf)
{
    extern __shared__ float smem[];
    int tid = threadIdx.x, lane = tid & 31, warp = tid >> 5;

    if (blockIdx.x >= NLSTM) {
        // ================= GEMM worker role =================
        float* a_s = smem;
        float* b_s = smem + 3 * 128 * LDP;
        __shared__ unsigned int s_w;
        const int K = Hz, N = G4z;

        int warp_m = warp & 1, warp_n = warp >> 1;
        int tile = lane >> 3, tr = lane & 7;
        int rowsel = (tile & 2) ? 8 : 0;
        int colsel = (tile & 1) ? 4 : 0;
        unsigned int aOff = (unsigned int)(((warp_m * 64 + rowsel + tr) * LDP
                                            + colsel) * 4);
        unsigned int bOff = (unsigned int)(((warp_n * 32 + rowsel + tr) * LDP
                                            + colsel) * 4);
        int qr = lane >> 2, qc = lane & 3;

        for (;;) {
            if (tid == 0) s_w = atomicAdd(&g_work[0], 1u);
            __syncthreads();
            unsigned int w = s_w;
            if (w >= 4096u) break;

            int grp = w >> 8;
            int within = w & 255;
            int dir = grp & 1;
            int c = grp >> 1;
            int chunk = dir ? (7 - c) : c;
            int b = within >> 4;
            int nt = within & 15;
            int m0 = b * 1024 + chunk * 128;
            int n0 = nt * 128;
            const float* W = dir ? Wb : Wf;
            const float* bias = dir ? bb : bf;
            float* C = dir ? xgb : xgf;

            float acc[4][4][4];
#pragma unroll
            for (int i = 0; i < 4; ++i)
#pragma unroll
                for (int j = 0; j < 4; ++j)
#pragma unroll
                    for (int r = 0; r < 4; ++r) acc[i][j][r] = 0.f;

#define ISSUE(chunk_, stage_) do {                                         \
        int kofs = (chunk_) * 32;                                          \
        float* as = a_s + (stage_) * 128 * LDP;                            \
        float* bs = b_s + (stage_) * 128 * LDP;                            \
        _Pragma("unroll")                                                  \
        for (int i_ = 0; i_ < 4; ++i_) {                                   \
            int f_ = tid + 256 * i_;                                       \
            int row_ = f_ >> 3, q_ = f_ & 7;                               \
            cp_async16(&as[row_ * LDP + q_ * 4],                           \
                       &A[(size_t)(m0 + row_) * K + kofs + q_ * 4]);       \
            cp_async16(&bs[row_ * LDP + q_ * 4],                           \
                       &W[(size_t)(n0 + row_) * K + kofs + q_ * 4]);       \
        }                                                                  \
        CP_COMMIT();                                                       \
    } while (0)

            ISSUE(0, 0);
            ISSUE(1, 1);
            // single-sync multistage: WAIT -> bar -> ISSUE -> compute
            for (int kt = 0; kt < 32; ++kt) {
                CP_WAIT1();
                __syncthreads();
                if (kt + 2 < 32) {
                    ISSUE(kt + 2, (kt + 2) % 3);
                } else {
                    CP_COMMIT();
                }
                float* ab = a_s + (kt % 3) * 128 * LDP;
                float* bb2 = b_s + (kt % 3) * 128 * LDP;
                GEMM_CHUNK_LDSM(ab, bb2, aOff, bOff, acc);
            }

            __syncthreads();   // protect stage reuse by next tile's ISSUE(0/1)
#pragma unroll
            for (int i = 0; i < 4; ++i) {
                int r0 = m0 + warp_m * 64 + i * 16 + qr;
#pragma unroll
                for (int j = 0; j < 4; ++j) {
                    int c0 = n0 + warp_n * 32 + j * 8 + qc * 2;
                    float v0 = bias[c0], v1 = bias[c0 + 1];
                    C[(size_t)r0 * N + c0]           = acc[i][j][0] + v0;
                    C[(size_t)r0 * N + c0 + 1]       = acc[i][j][1] + v1;
                    C[(size_t)(r0 + 8) * N + c0]     = acc[i][j][2] + v0;
                    C[(size_t)(r0 + 8) * N + c0 + 1] = acc[i][j][3] + v1;
                }
            }
            __syncthreads();
            if (tid == 0) red_release(&g_prog[grp * 64], 1u);
        }
        return;
    }

    // ================= LSTM role =================
    float* h_sm  = smem;                 // 16 x 516
    float* red   = h_sm + 16 * 516;      // [8][32][17]
    float* c_sm  = red + 8 * 32 * 17;    // 128
    float* xg_sm = c_sm + 128;           // [2][4*128] prefetched gates

    int dir = blockIdx.x >> 6;
    int slice = blockIdx.x & 63;
    int j0 = slice << 3;
    const float* whh = dir ? whh_b : whh_f;
    const float* xg  = dir ? xgb : xgf;

    int qr = lane >> 2, qc = lane & 3;
    int kbase = warp << 6;
    int b = tid >> 3, jj = tid & 7;

    unsigned int wreg[8][4][2];
#pragma unroll
    for (int s = 0; s < 8; ++s)
#pragma unroll
        for (int j = 0; j < 4; ++j) {
            const float* wr = whh + (size_t)(j * HHz + j0 + qr) * HHz
                              + kbase + s * 8;
            wreg[s][j][0] = f2tf32(wr[qc]);
            wreg[s][j][1] = f2tf32(wr[qc + 4]);
        }

    if (tid < 128) c_sm[tid] = 0.f;
    __syncthreads();

    unsigned int* barp = &g_bar[dir * 64];

    // prologue: load step-0 h slab (zeros), gate chunk 0, prefetch xg step 0
    {
        const float* hgr = hbuf + (size_t)(dir * 2 + 0) * Bz * HHz;
        int q = lane & 15, bh = lane >> 4;
#pragma unroll
        for (int i = 0; i < 8; ++i) {
            int bb2 = i * 2 + bh;
            *(float4*)&h_sm[bb2 * 516 + kbase + q * 4] =
                *(const float4*)&hgr[bb2 * HHz + kbase + q * 4];
        }
        __syncwarp();

        unsigned int* pp = &g_prog[(0 * 2 + dir) * 64];
        while (ld_acquire(pp) < 256u) { }
        if (tid < 128) {
            int t0 = dir ? (Tz - 1) : 0;
            const float* xr = xg + ((size_t)b * Tz + t0) * G4z + j0 + jj;
            cp_async4(&xg_sm[tid],       xr);
            cp_async4(&xg_sm[128 + tid], xr + HHz);
            cp_async4(&xg_sm[256 + tid], xr + 2 * HHz);
            cp_async4(&xg_sm[384 + tid], xr + 3 * HHz);
        }
        CP_COMMIT();
    }

    for (int step = 0; step < Tz; ++step) {
        int par = step & 1;
        int t = dir ? (Tz - 1 - step) : step;

        // gate + prefetch xg for step+1 (consumed next iteration)
        if (step + 1 < Tz) {
            if (((step + 1) & 127) == 0) {
                unsigned int* pp = &g_prog[(((step + 1) >> 7) * 2 + dir) * 64];
                while (ld_acquire(pp) < 256u) { }
            }
            if (tid < 128) {
                int t1 = dir ? (Tz - 1 - (step + 1)) : (step + 1);
                const float* xr = xg + ((size_t)b * Tz + t1) * G4z + j0 + jj;
                float* xb = xg_sm + ((step + 1) & 1) * 512;
                cp_async4(&xb[tid],       xr);
                cp_async4(&xb[128 + tid], xr + HHz);
                cp_async4(&xb[256 + tid], xr + 2 * HHz);
                cp_async4(&xb[384 + tid], xr + 3 * HHz);
            }
        }
        CP_COMMIT();
        CP_WAIT1();   // current step's xg (committed last iteration) is ready

        float acc[4][4];
#pragma unroll
        for (int j = 0; j < 4; ++j)
#pragma unroll
            for (int r = 0; r < 4; ++r) acc[j][r] = 0.f;

#pragma unroll
        for (int s = 0; s < 8; ++s) {
            const float* hb = h_sm + kbase + s * 8;
            unsigned int a[4];
            a[0] = __float_as_uint(hb[qr * 516 + qc]);
            a[1] = __float_as_uint(hb[(qr + 8) * 516 + qc]);
            a[2] = __float_as_uint(hb[qr * 516 + qc + 4]);
            a[3] = __float_as_uint(hb[(qr + 8) * 516 + qc + 4]);
#pragma unroll
            for (int j = 0; j < 4; ++j)
                mma_tf32(acc[j], a, wreg[s][j]);
        }

        float* rw = red + warp * 32 * 17;
#pragma unroll
        for (int j = 0; j < 4; ++j) {
            int n0i = j * 8 + qc * 2;
            rw[n0i * 17 + qr]           = acc[j][0];
            rw[(n0i + 1) * 17 + qr]     = acc[j][1];
            rw[n0i * 17 + qr + 8]       = acc[j][2];
            rw[(n0i + 1) * 17 + qr + 8] = acc[j][3];
        }
        __syncthreads();

        float h = 0.f;
        if (tid < 128) {
            const float* xb = xg_sm + (step & 1) * 512;
            float gi = xb[tid], gf = xb[128 + tid];
            float gg = xb[256 + tid], go = xb[384 + tid];
#pragma unroll
            for (int w = 0; w < 8; ++w) {
                const float* rp = red + w * 32 * 17;
                gi += rp[jj * 17 + b];
                gf += rp[(8 + jj) * 17 + b];
                gg += rp[(16 + jj) * 17 + b];
                go += rp[(24 + jj) * 17 + b];
            }
            float i_ = sigmoid_fast(gi);
            float f_ = sigmoid_fast(gf);
            float g_ = tanh_fast(gg);
            float o_ = sigmoid_fast(go);
            float c = f_ * c_sm[tid] + i_ * g_;
            c_sm[tid] = c;
            h = o_ * tanh_fast(c);
            float* hw = hbuf + (size_t)(dir * 2 + (par ^ 1)) * Bz * HHz;
            hw[b * HHz + j0 + jj] = __uint_as_float(f2tf32(h));
        }

        if (step + 1 < Tz) {
            __syncthreads();
            if (tid == 0) red_release(barp, 1u);
            if (tid < 128)
                enc[((size_t)b * Tz + t) * Hz + dir * HHz + j0 + jj] = h;
            unsigned int target = (unsigned int)(step + 1) * 64u;
            while (ld_acquire(barp) < target) { }
            const float* hgr = hbuf + (size_t)(dir * 2 + (par ^ 1)) * Bz * HHz;
            int q = lane & 15, bh = lane >> 4;
#pragma unroll
            for (int i = 0; i < 8; ++i) {
                int bb2 = i * 2 + bh;
                *(float4*)&h_sm[bb2 * 516 + kbase + q * 4] =
                    *(const float4*)&hgr[bb2 * HHz + kbase + q * 4];
            }
            __syncwarp();
        } else {
            if (tid < 128)
                enc[((size_t)b * Tz + t) * Hz + dir * HHz + j0 + jj] = h;
        }
    }
}

// ---------------- pipelined tf32 GEMM 128x128, z-fused up to 3 -------------
#define STG 3
__global__ void __launch_bounds__(256) gemm_pipe(
    const float* __restrict__ A,
    const float* __restrict__ W0, const float* __restrict__ W1,
    const float* __restrict__ W2,
    const float* __restrict__ b0, const float* __restrict__ b1,
    const float* __restrict__ b2,
    float* __restrict__ C0, float* __restrict__ C1, float* __restrict__ C2,
    int M, int N, int K)
{
    extern __shared__ float sm[];
    float* a_s = sm;
    float* b_s = sm + STG * 128 * LDP;

    int z = blockIdx.z;
    const float* W   = (z == 0) ? W0 : (z == 1) ? W1 : W2;
    const float* bias= (z == 0) ? b0 : (z == 1) ? b1 : b2;
    float* C         = (z == 0) ? C0 : (z == 1) ? C1 : C2;

    int tid = threadIdx.x;
    int lane = tid & 31, warp = tid >> 5;
    int warp_m = warp & 1, warp_n = warp >> 1;
    int m0 = blockIdx.y * 128, n0 = blockIdx.x * 128;
    int qr = lane >> 2, qc = lane & 3;
    int nk = K >> 5;

    int tile = lane >> 3, tr = lane & 7;
    int rowsel = (tile & 2) ? 8 : 0;
    int colsel = (tile & 1) ? 4 : 0;
    unsigned int aOff = (unsigned int)(((warp_m * 64 + rowsel + tr) * LDP
                                        + colsel) * 4);
    unsigned int bOff = (unsigned int)(((warp_n * 32 + rowsel + tr) * LDP
                                        + colsel) * 4);

    float acc[4][4][4];
#pragma unroll
    for (int i = 0; i < 4; ++i)
#pragma unroll
        for (int j = 0; j < 4; ++j)
#pragma unroll
            for (int r = 0; r < 4; ++r) acc[i][j][r] = 0.f;

#define ISSUE_P(chunk, stage) do {                                         \
        int kofs = (chunk) * 32;                                           \
        float* as = a_s + (stage) * 128 * LDP;                             \
        float* bs = b_s + (stage) * 128 * LDP;                             \
        _Pragma("unroll")                                                  \
        for (int i_ = 0; i_ < 4; ++i_) {                                   \
            int f_ = tid + 256 * i_;                                       \
            int row_ = f_ >> 3, q_ = f_ & 7;                               \
            cp_async16(&as[row_ * LDP + q_ * 4],                           \
                       &A[(size_t)(m0 + row_) * K + kofs + q_ * 4]);       \
            cp_async16(&bs[row_ * LDP + q_ * 4],                           \
                       &W[(size_t)(n0 + row_) * K + kofs + q_ * 4]);       \
        }                                                                  \
        CP_COMMIT();                                                       \
    } while (0)

    ISSUE_P(0, 0);
    ISSUE_P(1, 1);

    for (int kt = 0; kt < nk; ++kt) {
        CP_WAIT1();
        __syncthreads();
        if (kt + 2 < nk) {
            ISSUE_P(kt + 2, (kt + 2) % STG);
        } else {
            CP_COMMIT();
        }
        float* ab = a_s + (kt % STG) * 128 * LDP;
        float* bb = b_s + (kt % STG) * 128 * LDP;
        GEMM_CHUNK_LDSM(ab, bb, aOff, bOff, acc);
    }

#pragma unroll
    for (int i = 0; i < 4; ++i) {
        int r0 = m0 + warp_m * 64 + i * 16 + qr;
#pragma unroll
        for (int j = 0; j < 4; ++j) {
            int c0 = n0 + warp_n * 32 + j * 8 + qc * 2;
            float bb0 = bias[c0], bb1 = bias[c0 + 1];
            C[(size_t)r0 * N + c0]           = acc[i][j][0] + bb0;
            C[(size_t)r0 * N + c0 + 1]       = acc[i][j][1] + bb1;
            C[(size_t)(r0 + 8) * N + c0]     = acc[i][j][2] + bb0;
            C[(size_t)(r0 + 8) * N + c0 + 1] = acc[i][j][3] + bb1;
        }
    }
}

// ---------------- span mean pool + layer norm ------------------------------
__global__ void __launch_bounds__(256) pool_ln_kernel(
    const float* __restrict__ enc, const int* __restrict__ heads,
    const int* __restrict__ tails, const float* __restrict__ g,
    const float* __restrict__ b, float* __restrict__ feat,
    float* __restrict__ feat32)
{
    __shared__ float rs[256], rq[256];
    int bs = blockIdx.x;
    int bb = bs >> 5;
    int tid = threadIdx.x;

    int head = heads[bs], tail = tails[bs];
    int s0 = head + 1; if (s0 < 0) s0 = 0;
    int s1 = tail; if (s1 > Tz) s1 = Tz;
    int n = s1 - s0; if (n < 0) n = 0;
    float inv = 1.f / (float)(n > 0 ? n : 1);

    float v[4];
#pragma unroll
    for (int i = 0; i < 4; ++i) v[i] = 0.f;
    for (int t = s0; t < s1; ++t) {
        const float* row = enc + ((size_t)bb * Tz + t) * Hz;
#pragma unroll
        for (int i = 0; i < 4; ++i) v[i] += row[tid + 256 * i];
    }
#pragma unroll
    for (int i = 0; i < 4; ++i) v[i] *= inv;

    float s = v[0] + v[1] + v[2] + v[3];
    float q = v[0]*v[0] + v[1]*v[1] + v[2]*v[2] + v[3]*v[3];
    rs[tid] = s; rq[tid] = q;
    __syncthreads();
    for (int off = 128; off > 0; off >>= 1) {
        if (tid < off) { rs[tid] += rs[tid + off]; rq[tid] += rq[tid + off]; }
        __syncthreads();
    }
    float mu = rs[0] * (1.f / Hz);
    float var = rq[0] * (1.f / Hz) - mu * mu;
    float rstd = rsqrtf(var + LN_EPS);

    float* out = feat + (size_t)bs * Hz;
    float* out32 = feat32 + (size_t)bs * Hz;
#pragma unroll
    for (int i = 0; i < 4; ++i) {
        int c = tid + 256 * i;
        float y = (v[i] - mu) * rstd * g[c] + b[c];
        out[c] = y;
        out32[c] = __uint_as_float(f2tf32(y));
    }
}

// ---------------- span self-attention --------------------------------------
__global__ void __launch_bounds__(256) attn_kernel(
    const float* __restrict__ Q, const float* __restrict__ K,
    const float* __restrict__ V, const int* __restrict__ amask,
    float* __restrict__ ctx)
{
    __shared__ float q_sm[Sz * 64], k_sm[Sz * 64], v_sm[Sz * 64];
    __shared__ int m_sm[Sz];
    int bh = blockIdx.x;
    int bb = bh >> 4, h = bh & 15;
    int tid = threadIdx.x, lane = tid & 31, warp = tid >> 5;

    for (int idx = tid; idx < Sz * 64; idx += 256) {
        int s = idx >> 6, d = idx & 63;
        size_t src = ((size_t)bb * Sz + s) * Hz + h * 64 + d;
        q_sm[idx] = Q[src];
        k_sm[idx] = K[src];
        v_sm[idx] = V[src];
    }
    if (tid < Sz) m_sm[tid] = amask[bb * Sz + tid];
    __syncthreads();

#pragma unroll
    for (int r = 0; r < 4; ++r) {
        int qi = warp + r * 8;
        int qm = m_sm[qi];
        float sc = 0.f;
#pragma unroll
        for (int d = 0; d < 64; ++d)
            sc += q_sm[qi * 64 + d] * k_sm[lane * 64 + d];
        sc *= 0.125f;
        int km = m_sm[lane];
        int valid = qm & km;
        if (!valid) sc = -FLT_MAX;
        float mx = sc;
#pragma unroll
        for (int o = 16; o > 0; o >>= 1)
            mx = fmaxf(mx, __shfl_xor_sync(0xffffffffu, mx, o));
        float e = __expf(sc - mx);
        float sum = e;
#pragma unroll
        for (int o = 16; o > 0; o >>= 1)
            sum += __shfl_xor_sync(0xffffffffu, sum, o);
        float p = e / sum;
        if (!valid) p = 0.f;
        float a0 = 0.f, a1 = 0.f;
#pragma unroll
        for (int kk = 0; kk < 32; ++kk) {
            float pk = __shfl_sync(0xffffffffu, p, kk);
            a0 += pk * v_sm[kk * 64 + lane];
            a1 += pk * v_sm[kk * 64 + lane + 32];
        }
        size_t dst = ((size_t)bb * Sz + qi) * Hz + h * 64;
        ctx[dst + lane] = __uint_as_float(f2tf32(a0));
        ctx[dst + lane + 32] = __uint_as_float(f2tf32(a1));
    }
}

// ---------------- residual add + layer norm --------------------------------
__global__ void __launch_bounds__(256) addln_kernel(
    const float* __restrict__ proj, const float* __restrict__ feat,
    const float* __restrict__ g, const float* __restrict__ b,
    float* __restrict__ out)
{
    __shared__ float rs[256], rq[256];
    int row = blockIdx.x, tid = threadIdx.x;
    const float* p = proj + (size_t)row * Hz;
    const float* f = feat + (size_t)row * Hz;
    float v[4];
#pragma unroll
    for (int i = 0; i < 4; ++i) {
        int c = tid + 256 * i;
        v[i] = p[c] + f[c];
    }
    float s = v[0] + v[1] + v[2] + v[3];
    float q = v[0]*v[0] + v[1]*v[1] + v[2]*v[2] + v[3]*v[3];
    rs[tid] = s; rq[tid] = q;
    __syncthreads();
    for (int off = 128; off > 0; off >>= 1) {
        if (tid < off) { rs[tid] += rs[tid + off]; rq[tid] += rq[tid + off]; }
        __syncthreads();
    }
    float mu = rs[0] * (1.f / Hz);
    float var = rq[0] * (1.f / Hz) - mu * mu;
    float rstd = rsqrtf(var + LN_EPS);
    float* o = out + (size_t)row * Hz;
#pragma unroll
    for (int i = 0; i < 4; ++i) {
        int c = tid + 256 * i;
        o[c] = (v[i] - mu) * rstd * g[c] + b[c];
    }
}

// ---------------- classifier ------------------------------------------------
__global__ void __launch_bounds__(128) cls_kernel(
    const float* __restrict__ att, const float* __restrict__ wc,
    const float* __restrict__ bc, float* __restrict__ out)
{
    __shared__ float red[128];
    int row = blockIdx.x, tid = threadIdx.x;
    const float* a = att + (size_t)row * Hz;
    for (int l = 0; l < NLz; ++l) {
        const float* w = wc + (size_t)l * Hz;
        float s = 0.f;
#pragma unroll
        for (int i = 0; i < 8; ++i)
            s += a[tid + 128 * i] * w[tid + 128 * i];
        red[tid] = s;
        __syncthreads();
        for (int off = 64; off > 0; off >>= 1) {
            if (tid < off) red[tid] += red[tid + off];
            __syncthreads();
        }
        if (tid == 0) out[row * NLz + l] = red[0] + bc[l];
        __syncthreads();
    }
}

// ---------------- launch -----------------------------------------------------
extern "C" void kernel_launch(void* const* d_in, const int* in_sizes, int n_in,
                              void* d_out, int out_size) {
    const float* hs     = (const float*)d_in[0];
    const float* w_ih_f = (const float*)d_in[1];
    const float* w_hh_f = (const float*)d_in[2];
    const float* b_f    = (const float*)d_in[3];
    const float* w_ih_b = (const float*)d_in[4];
    const float* w_hh_b = (const float*)d_in[5];
    const float* b_b    = (const float*)d_in[6];
    const float* ln_g   = (const float*)d_in[7];
    const float* ln_b   = (const float*)d_in[8];
    const float* wq     = (const float*)d_in[9];
    const float* bq     = (const float*)d_in[10];
    const float* wk     = (const float*)d_in[11];
    const float* bk     = (const float*)d_in[12];
    const float* wv     = (const float*)d_in[13];
    const float* bv     = (const float*)d_in[14];
    const float* wo     = (const float*)d_in[15];
    const float* bo     = (const float*)d_in[16];
    const float* aln_g  = (const float*)d_in[17];
    const float* aln_b  = (const float*)d_in[18];
    const float* wc     = (const float*)d_in[19];
    const float* bc     = (const float*)d_in[20];
    const int* heads    = (const int*)d_in[21];
    const int* tails    = (const int*)d_in[22];
    const int* amask    = (const int*)d_in[23];
    float* out = (float*)d_out;

    float *xgf, *xgb, *enc, *hbuf, *feat, *feat32, *q, *k, *v, *ctx, *proj, *att;
    float *hs32, *wihf32, *wihb32, *wq32, *wk32, *wv32, *wo32;
    cudaGetSymbolAddress((void**)&xgf,  g_xgf);
    cudaGetSymbolAddress((void**)&xgb,  g_xgb);
    cudaGetSymbolAddress((void**)&enc,  g_enc);
    cudaGetSymbolAddress((void**)&hbuf, g_hbuf);
    cudaGetSymbolAddress((void**)&feat, g_feat);
    cudaGetSymbolAddress((void**)&feat32, g_feat32);
    cudaGetSymbolAddress((void**)&q,    g_q);
    cudaGetSymbolAddress((void**)&k,    g_k);
    cudaGetSymbolAddress((void**)&v,    g_v);
    cudaGetSymbolAddress((void**)&ctx,  g_ctx);
    cudaGetSymbolAddress((void**)&proj, g_proj);
    cudaGetSymbolAddress((void**)&att,  g_att);
    cudaGetSymbolAddress((void**)&hs32,   g_hs32);
    cudaGetSymbolAddress((void**)&wihf32, g_wihf32);
    cudaGetSymbolAddress((void**)&wihb32, g_wihb32);
    cudaGetSymbolAddress((void**)&wq32,   g_wq32);
    cudaGetSymbolAddress((void**)&wk32,   g_wk32);
    cudaGetSymbolAddress((void**)&wv32,   g_wv32);
    cudaGetSymbolAddress((void**)&wo32,   g_wo32);

    cudaFuncSetAttribute(fused_kernel,
                         cudaFuncAttributeMaxDynamicSharedMemorySize, FSM_BYTES);
    const int gemm_smem = STG * 128 * LDP * 2 * 4;
    cudaFuncSetAttribute(gemm_pipe,
                         cudaFuncAttributeMaxDynamicSharedMemorySize, gemm_smem);

    init_kernel<<<32, 256>>>();                                           // 1
    conv_pre3<<<dim3(512, 3), 256>>>(hs, hs32, (Bz * Tz * Hz) / 4,
                                     w_ih_f, wihf32, (G4z * Hz) / 4,
                                     w_ih_b, wihb32, (G4z * Hz) / 4);     // 2
    conv_tf32_4<<<dim3(128, 4), 256>>>(wq, wq32, wk, wk32, wv, wv32,
                                       wo, wo32, (Hz * Hz) / 4);          // 3
    fused_kernel<<<296, 256, FSM_BYTES>>>(
        hs32, wihf32, wihb32, b_f, b_b, xgf, xgb,
        w_hh_f, w_hh_b, enc, hbuf);                                       // 4
    pool_ln_kernel<<<Bz * Sz, 256>>>(enc, heads, tails, ln_g, ln_b,
                                     feat, feat32);                       // 5
    gemm_pipe<<<dim3(Hz / 128, (Bz * Sz) / 128, 3), 256, gemm_smem>>>(
        feat32, wq32, wk32, wv32, bq, bk, bv,
        q, k, v, Bz * Sz, Hz, Hz);                                        // 6
    attn_kernel<<<Bz * NHz, 256>>>(q, k, v, amask, ctx);                  // 7
    gemm_pipe<<<dim3(Hz / 128, (Bz * Sz) / 128, 1), 256, gemm_smem>>>(
        ctx, wo32, nullptr, nullptr, bo, nullptr, nullptr,
        proj, nullptr, nullptr, Bz * Sz, Hz, Hz);                         // 8
    addln_kernel<<<Bz * Sz, 256>>>(proj, feat, aln_g, aln_b, att);        // 9
    cls_kernel<<<Bz * Sz, 128>>>(att, wc, bc, out);                       // 10
}

// round 15
// speedup vs baseline: 1.1641x; 1.0673x over previous
#include <cuda_runtime.h>
#include <math.h>
#include <float.h>
#include <stdint.h>
#include <stddef.h>

#define Bz 16
#define Tz 1024
#define Hz 1024
#define HHz 512
#define Sz 32
#define NHz 16
#define NLz 3
#define G4z 2048
#define LN_EPS 1e-7f

// ---------------- scratch ----------------
__device__ float g_xgf[(size_t)Bz * Tz * G4z];
__device__ float g_xgb[(size_t)Bz * Tz * G4z];
__device__ float g_enc[(size_t)Bz * Tz * Hz];
__device__ float g_hbuf[2 * 2 * Bz * HHz];
__device__ float g_feat[Bz * Sz * Hz];
__device__ float g_feat32[Bz * Sz * Hz];
__device__ float g_q[Bz * Sz * Hz];
__device__ float g_k[Bz * Sz * Hz];
__device__ float g_v[Bz * Sz * Hz];
__device__ float g_ctx[Bz * Sz * Hz];
__device__ float g_proj[Bz * Sz * Hz];
__device__ float g_att[Bz * Sz * Hz];
__device__ unsigned int g_bar[128];        // dir*64 -> 256B apart
__device__ unsigned int g_work[32];
__device__ unsigned int g_prog[16 * 64];   // grp*64 -> 256B apart
__device__ float g_hs32[(size_t)Bz * Tz * Hz];
__device__ float g_wihf32[(size_t)G4z * Hz];
__device__ float g_wihb32[(size_t)G4z * Hz];
__device__ float g_wq32[Hz * Hz];
__device__ float g_wk32[Hz * Hz];
__device__ float g_wv32[Hz * Hz];
__device__ float g_wo32[Hz * Hz];

// ---------------- helpers ----------------
__device__ __forceinline__ unsigned int f2tf32(float x) {
    unsigned int u;
    asm("cvt.rna.tf32.f32 %0, %1;" : "=r"(u) : "f"(x));
    return u;
}
__device__ __forceinline__ float tanh_fast(float x) {
    float y;
    asm("tanh.approx.f32 %0, %1;" : "=f"(y) : "f"(x));
    return y;
}
__device__ __forceinline__ float sigmoid_fast(float x) {
    return 0.5f * tanh_fast(0.5f * x) + 0.5f;
}
__device__ __forceinline__ void mma_tf32(float* d, const unsigned int* a,
                                         const unsigned int* b) {
    asm("mma.sync.aligned.m16n8k8.row.col.f32.tf32.tf32.f32 "
        "{%0,%1,%2,%3}, {%4,%5,%6,%7}, {%8,%9}, {%0,%1,%2,%3};"
        : "+f"(d[0]), "+f"(d[1]), "+f"(d[2]), "+f"(d[3])
        : "r"(a[0]), "r"(a[1]), "r"(a[2]), "r"(a[3]), "r"(b[0]), "r"(b[1]));
}
__device__ __forceinline__ void ldsm_x4(unsigned int* r, unsigned int addr) {
    asm volatile("ldmatrix.sync.aligned.m8n8.x4.shared.b16 {%0,%1,%2,%3}, [%4];"
                 : "=r"(r[0]), "=r"(r[1]), "=r"(r[2]), "=r"(r[3]) : "r"(addr));
}
__device__ __forceinline__ void cp_async16(void* dst, const void* src) {
    unsigned int d = (unsigned int)__cvta_generic_to_shared(dst);
    asm volatile("cp.async.cg.shared.global [%0], [%1], 16;" :: "r"(d), "l"(src));
}
__device__ __forceinline__ void cp_async4(void* dst, const void* src) {
    unsigned int d = (unsigned int)__cvta_generic_to_shared(dst);
    asm volatile("cp.async.ca.shared.global [%0], [%1], 4;" :: "r"(d), "l"(src));
}
#define CP_COMMIT() asm volatile("cp.async.commit_group;")
#define CP_WAIT1()  asm volatile("cp.async.wait_group 1;")

__device__ __forceinline__ void red_release(unsigned int* p, unsigned int v) {
    asm volatile("red.release.gpu.global.add.u32 [%0], %1;" :: "l"(p), "r"(v)
                 : "memory");
}
__device__ __forceinline__ unsigned int ld_acquire(const unsigned int* p) {
    unsigned int v;
    asm volatile("ld.acquire.gpu.global.u32 %0, [%1];" : "=r"(v) : "l"(p)
                 : "memory");
    return v;
}

// ---------------- init ----------------
__global__ void init_kernel() {
    int tid = blockIdx.x * blockDim.x + threadIdx.x;
    if (tid < 128) g_bar[tid] = 0u;
    if (tid < 32) g_work[tid] = 0u;
    for (int i = tid; i < 16 * 64; i += gridDim.x * blockDim.x) g_prog[i] = 0u;
    for (int i = tid; i < 2 * 2 * Bz * HHz; i += gridDim.x * blockDim.x)
        g_hbuf[i] = 0.f;
}

// ---------------- tf32 pre-convert ----------------
__global__ void conv_pre3(const float* s0, float* d0, int n0,
                          const float* s1, float* d1, int n1,
                          const float* s2, float* d2, int n2) {
    int y = blockIdx.y;
    const float* s = (y == 0) ? s0 : (y == 1) ? s1 : s2;
    float* d = (y == 0) ? d0 : (y == 1) ? d1 : d2;
    int n4 = (y == 0) ? n0 : (y == 1) ? n1 : n2;
    int i = blockIdx.x * blockDim.x + threadIdx.x;
    int stride = gridDim.x * blockDim.x;
    for (; i < n4; i += stride) {
        float4 v = ((const float4*)s)[i];
        v.x = __uint_as_float(f2tf32(v.x));
        v.y = __uint_as_float(f2tf32(v.y));
        v.z = __uint_as_float(f2tf32(v.z));
        v.w = __uint_as_float(f2tf32(v.w));
        ((float4*)d)[i] = v;
    }
}
__global__ void conv_tf32_4(const float* s0, float* d0, const float* s1, float* d1,
                            const float* s2, float* d2, const float* s3, float* d3,
                            int n4) {
    const float* s = (blockIdx.y == 0) ? s0 : (blockIdx.y == 1) ? s1
                    : (blockIdx.y == 2) ? s2 : s3;
    float* d = (blockIdx.y == 0) ? d0 : (blockIdx.y == 1) ? d1
             : (blockIdx.y == 2) ? d2 : d3;
    int i = blockIdx.x * blockDim.x + threadIdx.x;
    int stride = gridDim.x * blockDim.x;
    for (; i < n4; i += stride) {
        float4 v = ((const float4*)s)[i];
        v.x = __uint_as_float(f2tf32(v.x));
        v.y = __uint_as_float(f2tf32(v.y));
        v.z = __uint_as_float(f2tf32(v.z));
        v.w = __uint_as_float(f2tf32(v.w));
        ((float4*)d)[i] = v;
    }
}

// inner compute step shared by both GEMM paths: one 32-wide k-chunk with LDSM
#define GEMM_CHUNK_LDSM(ab, bb2, aBaseOff, bBaseOff, ACC) do {               \
    unsigned int aB = (unsigned int)__cvta_generic_to_shared(ab) + aBaseOff; \
    unsigned int bB = (unsigned int)__cvta_generic_to_shared(bb2) + bBaseOff;\
    _Pragma("unroll")                                                        \
    for (int ks = 0; ks < 4; ++ks) {                                         \
        unsigned int koff = ks * 32;                                         \
        unsigned int afr[4][4];                                              \
        _Pragma("unroll")                                                    \
        for (int i = 0; i < 4; ++i) {                                        \
            unsigned int av[4];                                              \
            ldsm_x4(av, aB + (unsigned int)(i * 16 * LDP * 4) + koff);       \
            afr[i][0] = av[0]; afr[i][1] = av[2];                            \
            afr[i][2] = av[1]; afr[i][3] = av[3];                            \
        }                                                                    \
        unsigned int bv0[4], bv1[4];                                         \
        ldsm_x4(bv0, bB + koff);                                             \
        ldsm_x4(bv1, bB + (unsigned int)(16 * LDP * 4) + koff);              \
        _Pragma("unroll")                                                    \
        for (int i = 0; i < 4; ++i) {                                        \
            mma_tf32(ACC[i][0], afr[i], &bv0[0]);                            \
            mma_tf32(ACC[i][1], afr[i], &bv0[2]);                            \
            mma_tf32(ACC[i][2], afr[i], &bv1[0]);                            \
            mma_tf32(ACC[i][3], afr[i], &bv1[2]);                            \
        }                                                                    \
    }                                                                        \
} while (0)

// ---------------- FUSED gate-GEMM + bi-LSTM ---------------------------------
#define LDP 36
#define NLSTM 128
#define FSM_BYTES (3 * 2 * 128 * LDP * 4)   // 110592
__global__ void __launch_bounds__(256, 2) fused_kernel(
    const float* __restrict__ A,
    const float* __restrict__ Wf, const float* __restrict__ Wb,
    const float* __restrict__ bf, const float* __restrict__ bb,
    float* __restrict__ xgf, float* __restrict__ xgb,
    const float* __restrict__ whh_f, const float* __restrict__ whh_b,
    float* __restrict__ enc, float* __restrict__ hbuf)
{
    extern __shared__ float smem[];
    int tid = threadIdx.x, lane = tid & 31, warp = tid >> 5;

    if (blockIdx.x >= NLSTM) {
        // ================= GEMM worker role =================
        float* a_s = smem;
        float* b_s = smem + 3 * 128 * LDP;
        __shared__ unsigned int s_w;
        const int K = Hz, N = G4z;

        int warp_m = warp & 1, warp_n = warp >> 1;
        int tile = lane >> 3, tr = lane & 7;
        int rowsel = (tile & 2) ? 8 : 0;
        int colsel = (tile & 1) ? 4 : 0;
        unsigned int aOff = (unsigned int)(((warp_m * 64 + rowsel + tr) * LDP
                                            + colsel) * 4);
        unsigned int bOff = (unsigned int)(((warp_n * 32 + rowsel + tr) * LDP
                                            + colsel) * 4);
        int qr = lane >> 2, qc = lane & 3;

        for (;;) {
            if (tid == 0) s_w = atomicAdd(&g_work[0], 1u);
            __syncthreads();
            unsigned int w = s_w;
            if (w >= 4096u) break;

            int grp = w >> 8;
            int within = w & 255;
            int dir = grp & 1;
            int c = grp >> 1;
            int chunk = dir ? (7 - c) : c;
            int b = within >> 4;
            int nt = within & 15;
            int m0 = b * 1024 + chunk * 128;
            int n0 = nt * 128;
            const float* W = dir ? Wb : Wf;
            const float* bias = dir ? bb : bf;
            float* C = dir ? xgb : xgf;

            float acc[4][4][4];
#pragma unroll
            for (int i = 0; i < 4; ++i)
#pragma unroll
                for (int j = 0; j < 4; ++j)
#pragma unroll
                    for (int r = 0; r < 4; ++r) acc[i][j][r] = 0.f;

#define ISSUE(chunk_, stage_) do {                                         \
        int kofs = (chunk_) * 32;                                          \
        float* as = a_s + (stage_) * 128 * LDP;                            \
        float* bs = b_s + (stage_) * 128 * LDP;                            \
        _Pragma("unroll")                                                  \
        for (int i_ = 0; i_ < 4; ++i_) {                                   \
            int f_ = tid + 256 * i_;                                       \
            int row_ = f_ >> 3, q_ = f_ & 7;                               \
            cp_async16(&as[row_ * LDP + q_ * 4],                           \
                       &A[(size_t)(m0 + row_) * K + kofs + q_ * 4]);       \
            cp_async16(&bs[row_ * LDP + q_ * 4],                           \
                       &W[(size_t)(n0 + row_) * K + kofs + q_ * 4]);       \
        }                                                                  \
        CP_COMMIT();                                                       \
    } while (0)

            ISSUE(0, 0);
            ISSUE(1, 1);
            // single-sync multistage: WAIT -> bar -> ISSUE -> compute
            for (int kt = 0; kt < 32; ++kt) {
                CP_WAIT1();
                __syncthreads();
                if (kt + 2 < 32) {
                    ISSUE(kt + 2, (kt + 2) % 3);
                } else {
                    CP_COMMIT();
                }
                float* ab = a_s + (kt % 3) * 128 * LDP;
                float* bb2 = b_s + (kt % 3) * 128 * LDP;
                GEMM_CHUNK_LDSM(ab, bb2, aOff, bOff, acc);
            }

            __syncthreads();   // protect stage reuse by next tile's ISSUE(0/1)
#pragma unroll
            for (int i = 0; i < 4; ++i) {
                int r0 = m0 + warp_m * 64 + i * 16 + qr;
#pragma unroll
                for (int j = 0; j < 4; ++j) {
                    int c0 = n0 + warp_n * 32 + j * 8 + qc * 2;
                    float v0 = bias[c0], v1 = bias[c0 + 1];
                    C[(size_t)r0 * N + c0]           = acc[i][j][0] + v0;
                    C[(size_t)r0 * N + c0 + 1]       = acc[i][j][1] + v1;
                    C[(size_t)(r0 + 8) * N + c0]     = acc[i][j][2] + v0;
                    C[(size_t)(r0 + 8) * N + c0 + 1] = acc[i][j][3] + v1;
                }
            }
            __syncthreads();
            if (tid == 0) red_release(&g_prog[grp * 64], 1u);
        }
        return;
    }

    // ================= LSTM role =================
    float* h_sm  = smem;                 // 16 x 516
    float* red   = h_sm + 16 * 516;      // [8][32][17]
    float* c_sm  = red + 8 * 32 * 17;    // 128
    float* xg_sm = c_sm + 128;           // [2][4*128] prefetched gates

    int dir = blockIdx.x >> 6;
    int slice = blockIdx.x & 63;
    int j0 = slice << 3;
    const float* whh = dir ? whh_b : whh_f;
    const float* xg  = dir ? xgb : xgf;

    int qr = lane >> 2, qc = lane & 3;
    int kbase = warp << 6;
    int b = tid >> 3, jj = tid & 7;

    unsigned int wreg[8][4][2];
#pragma unroll
    for (int s = 0; s < 8; ++s)
#pragma unroll
        for (int j = 0; j < 4; ++j) {
            const float* wr = whh + (size_t)(j * HHz + j0 + qr) * HHz
                              + kbase + s * 8;
            wreg[s][j][0] = f2tf32(wr[qc]);
            wreg[s][j][1] = f2tf32(wr[qc + 4]);
        }

    if (tid < 128) c_sm[tid] = 0.f;
    __syncthreads();

    unsigned int* barp = &g_bar[dir * 64];

    // prologue: load step-0 h slab (zeros), gate chunk 0, prefetch xg step 0
    {
        const float* hgr = hbuf + (size_t)(dir * 2 + 0) * Bz * HHz;
        int q = lane & 15, bh = lane >> 4;
#pragma unroll
        for (int i = 0; i < 8; ++i) {
            int bb2 = i * 2 + bh;
            *(float4*)&h_sm[bb2 * 516 + kbase + q * 4] =
                *(const float4*)&hgr[bb2 * HHz + kbase + q * 4];
        }
        __syncwarp();

        unsigned int* pp = &g_prog[(0 * 2 + dir) * 64];
        while (ld_acquire(pp) < 256u) { }
        if (tid < 128) {
            int t0 = dir ? (Tz - 1) : 0;
            const float* xr = xg + ((size_t)b * Tz + t0) * G4z + j0 + jj;
            cp_async4(&xg_sm[tid],       xr);
            cp_async4(&xg_sm[128 + tid], xr + HHz);
            cp_async4(&xg_sm[256 + tid], xr + 2 * HHz);
            cp_async4(&xg_sm[384 + tid], xr + 3 * HHz);
        }
        CP_COMMIT();
    }

    for (int step = 0; step < Tz; ++step) {
        int par = step & 1;
        int t = dir ? (Tz - 1 - step) : step;

        // gate + prefetch xg for step+1 (consumed next iteration)
        if (step + 1 < Tz) {
            if (((step + 1) & 127) == 0) {
                unsigned int* pp = &g_prog[(((step + 1) >> 7) * 2 + dir) * 64];
                while (ld_acquire(pp) < 256u) { }
            }
            if (tid < 128) {
                int t1 = dir ? (Tz - 1 - (step + 1)) : (step + 1);
                const float* xr = xg + ((size_t)b * Tz + t1) * G4z + j0 + jj;
                float* xb = xg_sm + ((step + 1) & 1) * 512;
                cp_async4(&xb[tid],       xr);
                cp_async4(&xb[128 + tid], xr + HHz);
                cp_async4(&xb[256 + tid], xr + 2 * HHz);
                cp_async4(&xb[384 + tid], xr + 3 * HHz);
            }
        }
        CP_COMMIT();
        CP_WAIT1();   // current step's xg (committed last iteration) is ready

        float acc[4][4];
#pragma unroll
        for (int j = 0; j < 4; ++j)
#pragma unroll
            for (int r = 0; r < 4; ++r) acc[j][r] = 0.f;

#pragma unroll
        for (int s = 0; s < 8; ++s) {
            const float* hb = h_sm + kbase + s * 8;
            unsigned int a[4];
            a[0] = __float_as_uint(hb[qr * 516 + qc]);
            a[1] = __float_as_uint(hb[(qr + 8) * 516 + qc]);
            a[2] = __float_as_uint(hb[qr * 516 + qc + 4]);
            a[3] = __float_as_uint(hb[(qr + 8) * 516 + qc + 4]);
#pragma unroll
            for (int j = 0; j < 4; ++j)
                mma_tf32(acc[j], a, wreg[s][j]);
        }

        float* rw = red + warp * 32 * 17;
#pragma unroll
        for (int j = 0; j < 4; ++j) {
            int n0i = j * 8 + qc * 2;
            rw[n0i * 17 + qr]           = acc[j][0];
            rw[(n0i + 1) * 17 + qr]     = acc[j][1];
            rw[n0i * 17 + qr + 8]       = acc[j][2];
            rw[(n0i + 1) * 17 + qr + 8] = acc[j][3];
        }
        __syncthreads();

        float h = 0.f;
        if (tid < 128) {
            const float* xb = xg_sm + (step & 1) * 512;
            float gi = xb[tid], gf = xb[128 + tid];
            float gg = xb[256 + tid], go = xb[384 + tid];
#pragma unroll
            for (int w = 0; w < 8; ++w) {
                const float* rp = red + w * 32 * 17;
                gi += rp[jj * 17 + b];
                gf += rp[(8 + jj) * 17 + b];
                gg += rp[(16 + jj) * 17 + b];
                go += rp[(24 + jj) * 17 + b];
            }
            float i_ = sigmoid_fast(gi);
            float f_ = sigmoid_fast(gf);
            float g_ = tanh_fast(gg);
            float o_ = sigmoid_fast(go);
            float c = f_ * c_sm[tid] + i_ * g_;
            c_sm[tid] = c;
            h = o_ * tanh_fast(c);
            float* hw = hbuf + (size_t)(dir * 2 + (par ^ 1)) * Bz * HHz;
            hw[b * HHz + j0 + jj] = __uint_as_float(f2tf32(h));
        }

        if (step + 1 < Tz) {
            __syncthreads();
            if (tid == 0) red_release(barp, 1u);
            if (tid < 128)
                enc[((size_t)b * Tz + t) * Hz + dir * HHz + j0 + jj] = h;
            unsigned int target = (unsigned int)(step + 1) * 64u;
            while (ld_acquire(barp) < target) { }
            const float* hgr = hbuf + (size_t)(dir * 2 + (par ^ 1)) * Bz * HHz;
            int q = lane & 15, bh = lane >> 4;
#pragma unroll
            for (int i = 0; i < 8; ++i) {
                int bb2 = i * 2 + bh;
                *(float4*)&h_sm[bb2 * 516 + kbase + q * 4] =
                    *(const float4*)&hgr[bb2 * HHz + kbase + q * 4];
            }
            __syncwarp();
        } else {
            if (tid < 128)
                enc[((size_t)b * Tz + t) * Hz + dir * HHz + j0 + jj] = h;
        }
    }
}

// ---------------- pipelined tf32 GEMM 128x128, z-fused up to 3 -------------
#define STG 3
__global__ void __launch_bounds__(256) gemm_pipe(
    const float* __restrict__ A,
    const float* __restrict__ W0, const float* __restrict__ W1,
    const float* __restrict__ W2,
    const float* __restrict__ b0, const float* __restrict__ b1,
    const float* __restrict__ b2,
    float* __restrict__ C0, float* __restrict__ C1, float* __restrict__ C2,
    int M, int N, int K)
{
    extern __shared__ float sm[];
    float* a_s = sm;
    float* b_s = sm + STG * 128 * LDP;

    int z = blockIdx.z;
    const float* W   = (z == 0) ? W0 : (z == 1) ? W1 : W2;
    const float* bias= (z == 0) ? b0 : (z == 1) ? b1 : b2;
    float* C         = (z == 0) ? C0 : (z == 1) ? C1 : C2;

    int tid = threadIdx.x;
    int lane = tid & 31, warp = tid >> 5;
    int warp_m = warp & 1, warp_n = warp >> 1;
    int m0 = blockIdx.y * 128, n0 = blockIdx.x * 128;
    int qr = lane >> 2, qc = lane & 3;
    int nk = K >> 5;

    int tile = lane >> 3, tr = lane & 7;
    int rowsel = (tile & 2) ? 8 : 0;
    int colsel = (tile & 1) ? 4 : 0;
    unsigned int aOff = (unsigned int)(((warp_m * 64 + rowsel + tr) * LDP
                                        + colsel) * 4);
    unsigned int bOff = (unsigned int)(((warp_n * 32 + rowsel + tr) * LDP
                                        + colsel) * 4);

    float acc[4][4][4];
#pragma unroll
    for (int i = 0; i < 4; ++i)
#pragma unroll
        for (int j = 0; j < 4; ++j)
#pragma unroll
            for (int r = 0; r < 4; ++r) acc[i][j][r] = 0.f;

#define ISSUE_P(chunk, stage) do {                                         \
        int kofs = (chunk) * 32;                                           \
        float* as = a_s + (stage) * 128 * LDP;                             \
        float* bs = b_s + (stage) * 128 * LDP;                             \
        _Pragma("unroll")                                                  \
        for (int i_ = 0; i_ < 4; ++i_) {                                   \
            int f_ = tid + 256 * i_;                                       \
            int row_ = f_ >> 3, q_ = f_ & 7;                               \
            cp_async16(&as[row_ * LDP + q_ * 4],                           \
                       &A[(size_t)(m0 + row_) * K + kofs + q_ * 4]);       \
            cp_async16(&bs[row_ * LDP + q_ * 4],                           \
                       &W[(size_t)(n0 + row_) * K + kofs + q_ * 4]);       \
        }                                                                  \
        CP_COMMIT();                                                       \
    } while (0)

    ISSUE_P(0, 0);
    ISSUE_P(1, 1);

    for (int kt = 0; kt < nk; ++kt) {
        CP_WAIT1();
        __syncthreads();
        if (kt + 2 < nk) {
            ISSUE_P(kt + 2, (kt + 2) % STG);
        } else {
            CP_COMMIT();
        }
        float* ab = a_s + (kt % STG) * 128 * LDP;
        float* bb = b_s + (kt % STG) * 128 * LDP;
        GEMM_CHUNK_LDSM(ab, bb, aOff, bOff, acc);
    }

#pragma unroll
    for (int i = 0; i < 4; ++i) {
        int r0 = m0 + warp_m * 64 + i * 16 + qr;
#pragma unroll
        for (int j = 0; j < 4; ++j) {
            int c0 = n0 + warp_n * 32 + j * 8 + qc * 2;
            float bb0 = bias[c0], bb1 = bias[c0 + 1];
            C[(size_t)r0 * N + c0]           = acc[i][j][0] + bb0;
            C[(size_t)r0 * N + c0 + 1]       = acc[i][j][1] + bb1;
            C[(size_t)(r0 + 8) * N + c0]     = acc[i][j][2] + bb0;
            C[(size_t)(r0 + 8) * N + c0 + 1] = acc[i][j][3] + bb1;
        }
    }
}

// ---------------- span mean pool + layer norm ------------------------------
__global__ void __launch_bounds__(256) pool_ln_kernel(
    const float* __restrict__ enc, const int* __restrict__ heads,
    const int* __restrict__ tails, const float* __restrict__ g,
    const float* __restrict__ b, float* __restrict__ feat,
    float* __restrict__ feat32)
{
    __shared__ float rs[256], rq[256];
    int bs = blockIdx.x;
    int bb = bs >> 5;
    int tid = threadIdx.x;

    int head = heads[bs], tail = tails[bs];
    int s0 = head + 1; if (s0 < 0) s0 = 0;
    int s1 = tail; if (s1 > Tz) s1 = Tz;
    int n = s1 - s0; if (n < 0) n = 0;
    float inv = 1.f / (float)(n > 0 ? n : 1);

    float v[4];
#pragma unroll
    for (int i = 0; i < 4; ++i) v[i] = 0.f;
    for (int t = s0; t < s1; ++t) {
        const float* row = enc + ((size_t)bb * Tz + t) * Hz;
#pragma unroll
        for (int i = 0; i < 4; ++i) v[i] += row[tid + 256 * i];
    }
#pragma unroll
    for (int i = 0; i < 4; ++i) v[i] *= inv;

    float s = v[0] + v[1] + v[2] + v[3];
    float q = v[0]*v[0] + v[1]*v[1] + v[2]*v[2] + v[3]*v[3];
    rs[tid] = s; rq[tid] = q;
    __syncthreads();
    for (int off = 128; off > 0; off >>= 1) {
        if (tid < off) { rs[tid] += rs[tid + off]; rq[tid] += rq[tid + off]; }
        __syncthreads();
    }
    float mu = rs[0] * (1.f / Hz);
    float var = rq[0] * (1.f / Hz) - mu * mu;
    float rstd = rsqrtf(var + LN_EPS);

    float* out = feat + (size_t)bs * Hz;
    float* out32 = feat32 + (size_t)bs * Hz;
#pragma unroll
    for (int i = 0; i < 4; ++i) {
        int c = tid + 256 * i;
        float y = (v[i] - mu) * rstd * g[c] + b[c];
        out[c] = y;
        out32[c] = __uint_as_float(f2tf32(y));
    }
}

// ---------------- span self-attention --------------------------------------
__global__ void __launch_bounds__(256) attn_kernel(
    const float* __restrict__ Q, const float* __restrict__ K,
    const float* __restrict__ V, const int* __restrict__ amask,
    float* __restrict__ ctx)
{
    __shared__ float q_sm[Sz * 64], k_sm[Sz * 64], v_sm[Sz * 64];
    __shared__ int m_sm[Sz];
    int bh = blockIdx.x;
    int bb = bh >> 4, h = bh & 15;
    int tid = threadIdx.x, lane = tid & 31, warp = tid >> 5;

    for (int idx = tid; idx < Sz * 64; idx += 256) {
        int s = idx >> 6, d = idx & 63;
        size_t src = ((size_t)bb * Sz + s) * Hz + h * 64 + d;
        q_sm[idx] = Q[src];
        k_sm[idx] = K[src];
        v_sm[idx] = V[src];
    }
    if (tid < Sz) m_sm[tid] = amask[bb * Sz + tid];
    __syncthreads();

#pragma unroll
    for (int r = 0; r < 4; ++r) {
        int qi = warp + r * 8;
        int qm = m_sm[qi];
        float sc = 0.f;
#pragma unroll
        for (int d = 0; d < 64; ++d)
            sc += q_sm[qi * 64 + d] * k_sm[lane * 64 + d];
        sc *= 0.125f;
        int km = m_sm[lane];
        int valid = qm & km;
        if (!valid) sc = -FLT_MAX;
        float mx = sc;
#pragma unroll
        for (int o = 16; o > 0; o >>= 1)
            mx = fmaxf(mx, __shfl_xor_sync(0xffffffffu, mx, o));
        float e = __expf(sc - mx);
        float sum = e;
#pragma unroll
        for (int o = 16; o > 0; o >>= 1)
            sum += __shfl_xor_sync(0xffffffffu, sum, o);
        float p = e / sum;
        if (!valid) p = 0.f;
        float a0 = 0.f, a1 = 0.f;
#pragma unroll
        for (int kk = 0; kk < 32; ++kk) {
            float pk = __shfl_sync(0xffffffffu, p, kk);
            a0 += pk * v_sm[kk * 64 + lane];
            a1 += pk * v_sm[kk * 64 + lane + 32];
        }
        size_t dst = ((size_t)bb * Sz + qi) * Hz + h * 64;
        ctx[dst + lane] = __uint_as_float(f2tf32(a0));
        ctx[dst + lane + 32] = __uint_as_float(f2tf32(a1));
    }
}

// ---------------- residual add + layer norm --------------------------------
__global__ void __launch_bounds__(256) addln_kernel(
    const float* __restrict__ proj, const float* __restrict__ feat,
    const float* __restrict__ g, const float* __restrict__ b,
    float* __restrict__ out)
{
    __shared__ float rs[256], rq[256];
    int row = blockIdx.x, tid = threadIdx.x;
    const float* p = proj + (size_t)row * Hz;
    const float* f = feat + (size_t)row * Hz;
    float v[4];
#pragma unroll
    for (int i = 0; i < 4; ++i) {
        int c = tid + 256 * i;
        v[i] = p[c] + f[c];
    }
    float s = v[0] + v[1] + v[2] + v[3];
    float q = v[0]*v[0] + v[1]*v[1] + v[2]*v[2] + v[3]*v[3];
    rs[tid] = s; rq[tid] = q;
    __syncthreads();
    for (int off = 128; off > 0; off >>= 1) {
        if (tid < off) { rs[tid] += rs[tid + off]; rq[tid] += rq[tid + off]; }
        __syncthreads();
    }
    float mu = rs[0] * (1.f / Hz);
    float var = rq[0] * (1.f / Hz) - mu * mu;
    float rstd = rsqrtf(var + LN_EPS);
    float* o = out + (size_t)row * Hz;
#pragma unroll
    for (int i = 0; i < 4; ++i) {
        int c = tid + 256 * i;
        o[c] = (v[i] - mu) * rstd * g[c] + b[c];
    }
}

// ---------------- classifier ------------------------------------------------
__global__ void __launch_bounds__(128) cls_kernel(
    const float* __restrict__ att, const float* __restrict__ wc,
    const float* __restrict__ bc, float* __restrict__ out)
{
    __shared__ float red[128];
    int row = blockIdx.x, tid = threadIdx.x;
    const float* a = att + (size_t)row * Hz;
    for (int l = 0; l < NLz; ++l) {
        const float* w = wc + (size_t)l * Hz;
        float s = 0.f;
#pragma unroll
        for (int i = 0; i < 8; ++i)
            s += a[tid + 128 * i] * w[tid + 128 * i];
        red[tid] = s;
        __syncthreads();
        for (int off = 64; off > 0; off >>= 1) {
            if (tid < off) red[tid] += red[tid + off];
            __syncthreads();
        }
        if (tid == 0) out[row * NLz + l] = red[0] + bc[l];
        __syncthreads();
    }
}

// ---------------- launch -----------------------------------------------------
extern "C" void kernel_launch(void* const* d_in, const int* in_sizes, int n_in,
                              void* d_out, int out_size) {
    const float* hs     = (const float*)d_in[0];
    const float* w_ih_f = (const float*)d_in[1];
    const float* w_hh_f = (const float*)d_in[2];
    const float* b_f    = (const float*)d_in[3];
    const float* w_ih_b = (const float*)d_in[4];
    const float* w_hh_b = (const float*)d_in[5];
    const float* b_b    = (const float*)d_in[6];
    const float* ln_g   = (const float*)d_in[7];
    const float* ln_b   = (const float*)d_in[8];
    const float* wq     = (const float*)d_in[9];
    const float* bq     = (const float*)d_in[10];
    const float* wk     = (const float*)d_in[11];
    const float* bk     = (const float*)d_in[12];
    const float* wv     = (const float*)d_in[13];
    const float* bv     = (const float*)d_in[14];
    const float* wo     = (const float*)d_in[15];
    const float* bo     = (const float*)d_in[16];
    const float* aln_g  = (const float*)d_in[17];
    const float* aln_b  = (const float*)d_in[18];
    const float* wc     = (const float*)d_in[19];
    const float* bc     = (const float*)d_in[20];
    const int* heads    = (const int*)d_in[21];
    const int* tails    = (const int*)d_in[22];
    const int* amask    = (const int*)d_in[23];
    float* out = (float*)d_out;

    float *xgf, *xgb, *enc, *hbuf, *feat, *feat32, *q, *k, *v, *ctx, *proj, *att;
    float *hs32, *wihf32, *wihb32, *wq32, *wk32, *wv32, *wo32;
    cudaGetSymbolAddress((void**)&xgf,  g_xgf);
    cudaGetSymbolAddress((void**)&xgb,  g_xgb);
    cudaGetSymbolAddress((void**)&enc,  g_enc);
    cudaGetSymbolAddress((void**)&hbuf, g_hbuf);
    cudaGetSymbolAddress((void**)&feat, g_feat);
    cudaGetSymbolAddress((void**)&feat32, g_feat32);
    cudaGetSymbolAddress((void**)&q,    g_q);
    cudaGetSymbolAddress((void**)&k,    g_k);
    cudaGetSymbolAddress((void**)&v,    g_v);
    cudaGetSymbolAddress((void**)&ctx,  g_ctx);
    cudaGetSymbolAddress((void**)&proj, g_proj);
    cudaGetSymbolAddress((void**)&att,  g_att);
    cudaGetSymbolAddress((void**)&hs32,   g_hs32);
    cudaGetSymbolAddress((void**)&wihf32, g_wihf32);
    cudaGetSymbolAddress((void**)&wihb32, g_wihb32);
    cudaGetSymbolAddress((void**)&wq32,   g_wq32);
    cudaGetSymbolAddress((void**)&wk32,   g_wk32);
    cudaGetSymbolAddress((void**)&wv32,   g_wv32);
    cudaGetSymbolAddress((void**)&wo32,   g_wo32);

    cudaFuncSetAttribute(fused_kernel,
                         cudaFuncAttributeMaxDynamicSharedMemorySize, FSM_BYTES);
    const int gemm_smem = STG * 128 * LDP * 2 * 4;
    cudaFuncSetAttribute(gemm_pipe,
                         cudaFuncAttributeMaxDynamicSharedMemorySize, gemm_smem);

    init_kernel<<<32, 256>>>();                                           // 1
    conv_pre3<<<dim3(512, 3), 256>>>(hs, hs32, (Bz * Tz * Hz) / 4,
                                     w_ih_f, wihf32, (G4z * Hz) / 4,
                                     w_ih_b, wihb32, (G4z * Hz) / 4);     // 2
    conv_tf32_4<<<dim3(128, 4), 256>>>(wq, wq32, wk, wk32, wv, wv32,
                                       wo, wo32, (Hz * Hz) / 4);          // 3
    fused_kernel<<<296, 256, FSM_BYTES>>>(
        hs32, wihf32, wihb32, b_f, b_b, xgf, xgb,
        w_hh_f, w_hh_b, enc, hbuf);                                       // 4
    pool_ln_kernel<<<Bz * Sz, 256>>>(enc, heads, tails, ln_g, ln_b,
                                     feat, feat32);                       // 5
    gemm_pipe<<<dim3(Hz / 128, (Bz * Sz) / 128, 3), 256, gemm_smem>>>(
        feat32, wq32, wk32, wv32, bq, bk, bv,
        q, k, v, Bz * Sz, Hz, Hz);                                        // 6
    attn_kernel<<<Bz * NHz, 256>>>(q, k, v, amask, ctx);                  // 7
    gemm_pipe<<<dim3(Hz / 128, (Bz * Sz) / 128, 1), 256, gemm_smem>>>(
        ctx, wo32, nullptr, nullptr, bo, nullptr, nullptr,
        proj, nullptr, nullptr, Bz * Sz, Hz, Hz);                         // 8
    addln_kernel<<<Bz * Sz, 256>>>(proj, feat, aln_g, aln_b, att);        // 9
    cls_kernel<<<Bz * Sz, 128>>>(att, wc, bc, out);                       // 10
}